// round 1
// baseline (speedup 1.0000x reference)
#include <cuda_runtime.h>
#include <math.h>
#include <float.h>

// Problem constants (fixed by reference setup)
#define NB    32
#define NA    8400
#define NCLS  20
#define NG    128
#define NTOPK 10
#define MAIN_BX 33                 // ceil(8400/256)
#define NPART (MAIN_BX*NB)         // 1056 partial blocks

// ---- static scratch (no allocations allowed) ----
static __device__ float  g_pred[(size_t)NB*NA*4];          // pred_xyxy px   (4.3 MB)
static __device__ float  g_sqclsT[(size_t)NB*NCLS*NA];     // sqrt(clip(cls)) transposed [b][c][a] (21.5 MB)
static __device__ float  g_align[(size_t)NB*NG*NA];        // align matrix   (137.6 MB)
static __device__ float  g_thresh[NB*NG];                  // per-gt topk threshold
static __device__ double g_part[NPART*6];                  // block partials

__device__ __forceinline__ float clampf(float x, float lo, float hi){ return fminf(fmaxf(x,lo),hi); }

// pairwise IoU, matches _pairwise_iou_xyxy (eps=1e-7, per-box area clipped at 0)
__device__ __forceinline__ float pair_iou(float px1,float py1,float px2,float py2,
                                          float tx1,float ty1,float tx2,float ty2){
    float iw = fminf(px2,tx2) - fmaxf(px1,tx1); iw = fmaxf(iw, 0.f);
    float ih = fminf(py2,ty2) - fmaxf(py1,ty1); ih = fmaxf(ih, 0.f);
    float inter = iw*ih;
    float pa = fmaxf((px2-px1)*(py2-py1), 0.f);
    float ta = fmaxf((tx2-tx1)*(ty2-ty1), 0.f);
    return inter / (pa + ta - inter + 1e-7f);
}

// CIoU loss, matches _ciou_loss (eps=1e-7)
__device__ __forceinline__ float ciou_loss(float px1,float py1,float px2,float py2,
                                           float tx1,float ty1,float tx2,float ty2){
    const float eps = 1e-7f;
    float iw = fminf(px2,tx2) - fmaxf(px1,tx1); iw = fmaxf(iw,0.f);
    float ih = fminf(py2,ty2) - fmaxf(py1,ty1); ih = fmaxf(ih,0.f);
    float inter = iw*ih;
    float pw = fmaxf(px2-px1,0.f), ph = fmaxf(py2-py1,0.f);
    float tw = fmaxf(tx2-tx1,0.f), th = fmaxf(ty2-ty1,0.f);
    float uni = pw*ph + tw*th - inter + eps;
    float iou = inter/uni;
    float dx = (px1+px2)*0.5f - (tx1+tx2)*0.5f;
    float dy = (py1+py2)*0.5f - (ty1+ty2)*0.5f;
    float d2 = dx*dx + dy*dy;
    float ew = fmaxf(fmaxf(px2,tx2)-fminf(px1,tx1),0.f);
    float eh = fmaxf(fmaxf(py2,ty2)-fminf(py1,ty1),0.f);
    float c2 = ew*ew + eh*eh + eps;
    float da = atanf(tw/(th+eps)) - atanf(pw/(ph+eps));
    float v  = 0.40528473456935108577f * da*da;   // 4/pi^2
    float av = v / (1.f - iou + v + eps);
    return 1.f - (iou - d2/c2 - av*v);
}

// ---------------- Stage A: DFL decode -> pred boxes (px) ----------------
__global__ void k_decode(const float* __restrict__ pd,
                         const float* __restrict__ anc,
                         const float* __restrict__ str){
    int i = blockIdx.x*blockDim.x + threadIdx.x;
    if (i >= NB*NA) return;
    int a = i % NA;
    const float4* x4 = reinterpret_cast<const float4*>(pd + (size_t)i*64);
    float d[4];
    #pragma unroll
    for (int s=0;s<4;s++){
        float v[16];
        #pragma unroll
        for (int q=0;q<4;q++){
            float4 f = x4[s*4+q];
            v[q*4+0]=f.x; v[q*4+1]=f.y; v[q*4+2]=f.z; v[q*4+3]=f.w;
        }
        float m = v[0];
        #pragma unroll
        for (int j=1;j<16;j++) m = fmaxf(m, v[j]);
        float se=0.f, sw=0.f;
        #pragma unroll
        for (int j=0;j<16;j++){ float e=__expf(v[j]-m); se+=e; sw+=e*(float)j; }
        d[s] = sw/se;
    }
    float ax = anc[2*a], ay = anc[2*a+1], st = str[a];
    float* o = g_pred + (size_t)i*4;
    o[0]=(ax-d[0])*st; o[1]=(ay-d[1])*st; o[2]=(ax+d[2])*st; o[3]=(ay+d[3])*st;
}

// ---------------- Stage A2: sqrt(clip(cls,0,1)) transposed to [b][c][a] ----------------
__global__ void k_sqcls(const float* __restrict__ cls){
    __shared__ float t[40][21];
    int b = blockIdx.y; int a0 = blockIdx.x*40; int tid = threadIdx.x;
    int al = tid/20, c = tid%20;
    t[al][c] = cls[((size_t)b*NA + a0+al)*NCLS + c];
    __syncthreads();
    int c2 = tid/40, a2 = tid%40;
    float v = clampf(t[a2][c2], 0.f, 1.f);
    g_sqclsT[((size_t)b*NCLS + c2)*NA + a0+a2] = sqrtf(v);
}

// ---------------- Stage B: align matrix + exact top-k threshold per gt ----------------
__global__ void k_align(const float* __restrict__ anc,
                        const float* __restrict__ str,
                        const float* __restrict__ gtb,
                        const int*   __restrict__ gtl){
    __shared__ float cand[256*NTOPK];   // 10.2 KB
    int b = blockIdx.y, g = blockIdx.x, tid = threadIdx.x;
    int lbl = gtl[b*NG+g];
    bool valid = (lbl >= 0);
    int lc = lbl < 0 ? 0 : (lbl > NCLS-1 ? NCLS-1 : lbl);
    const float* gb = gtb + ((size_t)(b*NG+g))*4;
    float gx1=gb[0], gy1=gb[1], gx2=gb[2], gy2=gb[3];
    float ga = fmaxf((gx2-gx1)*(gy2-gy1), 0.f);
    const float* pr  = g_pred   + (size_t)b*NA*4;
    const float* sq  = g_sqclsT + ((size_t)b*NCLS + lc)*NA;
    float*       out = g_align  + ((size_t)(b*NG+g))*NA;

    float r[NTOPK];
    #pragma unroll
    for (int j=0;j<NTOPK;j++) r[j] = -1.f;

    for (int a = tid; a < NA; a += 256){
        float al = 0.f;
        float st = str[a];
        float ax = anc[2*a]*st, ay = anc[2*a+1]*st;
        if (valid && ax>gx1 && ax<gx2 && ay>gy1 && ay<gy2){
            float px1=pr[(size_t)a*4+0], py1=pr[(size_t)a*4+1];
            float px2=pr[(size_t)a*4+2], py2=pr[(size_t)a*4+3];
            float iw = fminf(px2,gx2)-fmaxf(px1,gx1); iw=fmaxf(iw,0.f);
            float ih = fminf(py2,gy2)-fmaxf(py1,gy1); ih=fmaxf(ih,0.f);
            float inter = iw*ih;
            float pa = fmaxf((px2-px1)*(py2-py1),0.f);
            float iou = inter/(pa+ga-inter+1e-7f);
            iou = clampf(iou, 0.f, 1.f);
            float i2=iou*iou; float i6=i2*i2*i2;
            al = sq[a]*i6;
        }
        out[a] = al;
        // insert into per-thread sorted (desc) top-10
        if (al > r[NTOPK-1]){
            r[NTOPK-1] = al;
            #pragma unroll
            for (int j=NTOPK-1;j>0;j--){
                if (r[j] > r[j-1]){ float tmp=r[j-1]; r[j-1]=r[j]; r[j]=tmp; }
            }
        }
    }
    #pragma unroll
    for (int j=0;j<NTOPK;j++) cand[tid*NTOPK+j] = r[j];
    __syncthreads();

    // warp 0: exact k-th largest (with multiplicity) of the candidate multiset
    if (tid < 32){
        float t = FLT_MAX;
        float th = 0.f;
        #pragma unroll 1
        for (int iter=0; iter<NTOPK; iter++){
            float m = -1.f;
            for (int j=tid; j<256*NTOPK; j+=32){
                float v = cand[j];
                if (v < t && v > m) m = v;
            }
            #pragma unroll
            for (int o=16;o;o>>=1) m = fmaxf(m, __shfl_xor_sync(0xffffffffu, m, o));
            int c = 0;
            for (int j=tid; j<256*NTOPK; j+=32) c += (cand[j] >= m);
            #pragma unroll
            for (int o=16;o;o>>=1) c += __shfl_xor_sync(0xffffffffu, c, o);
            th = m;
            if (c >= NTOPK) break;
            t = m;
        }
        if (tid == 0) g_thresh[b*NG+g] = th;
    }
}

// ---------------- Stage C: per-anchor assignment + fused losses ----------------
__global__ void k_main(const float* __restrict__ cls,
                       const float* __restrict__ pd,
                       const float* __restrict__ anc,
                       const float* __restrict__ str,
                       const float* __restrict__ gtb,
                       const int*   __restrict__ gtl){
    __shared__ float sgt[NG*4];
    __shared__ float sth[NG];
    __shared__ int   slbl[NG];
    __shared__ int   svalid[NG];
    __shared__ double rd[256];

    int b = blockIdx.y;
    int tid = threadIdx.x;
    int a = blockIdx.x*256 + tid;

    for (int i=tid; i<NG; i+=256){
        const float* gb = gtb + ((size_t)(b*NG+i))*4;
        sgt[i*4+0]=gb[0]; sgt[i*4+1]=gb[1]; sgt[i*4+2]=gb[2]; sgt[i*4+3]=gb[3];
        int l = gtl[b*NG+i];
        svalid[i] = (l >= 0);
        slbl[i]   = l < 0 ? 0 : (l > NCLS-1 ? NCLS-1 : l);
        sth[i]    = g_thresh[b*NG+i];
    }
    __syncthreads();

    double accCls=0.0;
    double accBox=0.0, accDfl=0.0, accAsp=0.0, accTss=0.0;
    double accGate=0.0;

    if (a < NA){
        const float* prp = g_pred + ((size_t)b*NA + a)*4;
        float px1=prp[0], py1=prp[1], px2=prp[2], py2=prp[3];
        float st = str[a];
        float ax = anc[2*a]*st, ay = anc[2*a+1]*st;

        unsigned mask0=0, mask1=0, mask2=0, mask3=0;
        int claims = 0;
        int best = 0; float bestV = -1.f;
        const float* alp = g_align + (size_t)b*NG*NA + a;
        #pragma unroll 4
        for (int g=0; g<NG; g++){
            float al = alp[(size_t)g*NA];
            if (al > bestV){ bestV = al; best = g; }
            float gx1=sgt[g*4+0], gy1=sgt[g*4+1], gx2=sgt[g*4+2], gy2=sgt[g*4+3];
            bool ib = svalid[g] && ax>gx1 && ax<gx2 && ay>gy1 && ay<gy2;
            bool mk = ib && (al >= sth[g]);
            if (mk){
                claims++;
                unsigned bit = 1u << (g & 31);
                if      (g < 32) mask0 |= bit;
                else if (g < 64) mask1 |= bit;
                else if (g < 96) mask2 |= bit;
                else             mask3 |= bit;
            }
        }
        if (claims > 1){
            mask0=mask1=mask2=mask3=0;
            unsigned bit = 1u << (best & 31);
            if      (best < 32) mask0 = bit;
            else if (best < 64) mask1 = bit;
            else if (best < 96) mask2 = bit;
            else                mask3 = bit;
        }
        bool fg = (mask0|mask1|mask2|mask3) != 0u;
        int assigned = 0;
        if (fg){
            if      (mask0) assigned = __ffs(mask0)-1;
            else if (mask1) assigned = 32 + __ffs(mask1)-1;
            else if (mask2) assigned = 64 + __ffs(mask2)-1;
            else            assigned = 96 + __ffs(mask3)-1;
        }
        float tbx1=0.f, tby1=0.f, tbx2=0.f, tby2=0.f;
        float maxIou = 0.f;
        if (fg){
            tbx1=sgt[assigned*4+0]; tby1=sgt[assigned*4+1];
            tbx2=sgt[assigned*4+2]; tby2=sgt[assigned*4+3];
            maxIou = pair_iou(px1,py1,px2,py2, tbx1,tby1,tbx2,tby2);
        }
        float alMax = bestV;                       // align.max(0) (>= 0)
        float soft  = alMax * maxIou / fmaxf(alMax, 1e-9f);
        float w     = fg ? soft : 0.f;             // = ts.sum(-1) * fg
        accTss = (double)w;
        int pl = slbl[assigned];

        // ---- classification BCE over all NC classes ----
        const float4* cp4 = reinterpret_cast<const float4*>(cls + ((size_t)b*NA + a)*NCLS);
        double ca = 0.0;
        #pragma unroll
        for (int q=0;q<5;q++){
            float4 f = cp4[q];
            float pv[4] = {f.x, f.y, f.z, f.w};
            #pragma unroll
            for (int k=0;k<4;k++){
                int c = q*4+k;
                float p = clampf(pv[k], 1e-7f, 1.0f - 1e-7f);
                float tv = (fg && c==pl) ? w : 0.f;
                float term = -((1.f - tv)*logf(1.f - p));
                if (tv != 0.f) term -= tv*logf(p);
                ca += (double)term;
            }
        }
        accCls = ca;

        if (w > 0.f){
            // ---- CIoU box loss ----
            accBox = (double)(w * ciou_loss(px1,py1,px2,py2, tbx1,tby1,tbx2,tby2));
            // ---- DFL loss ----
            float tgt[4];
            tgt[0] = (ax - tbx1)/st;
            tgt[1] = (ay - tby1)/st;
            tgt[2] = (tbx2 - ax)/st;
            tgt[3] = (tby2 - ay)/st;
            const float4* x4 = reinterpret_cast<const float4*>(pd + ((size_t)b*NA + a)*64);
            float dfl = 0.f;
            #pragma unroll
            for (int s=0;s<4;s++){
                float v[16];
                #pragma unroll
                for (int q=0;q<4;q++){
                    float4 f = x4[s*4+q];
                    v[q*4+0]=f.x; v[q*4+1]=f.y; v[q*4+2]=f.z; v[q*4+3]=f.w;
                }
                float m = v[0];
                #pragma unroll
                for (int j=1;j<16;j++) m = fmaxf(m, v[j]);
                float se = 0.f;
                #pragma unroll
                for (int j=0;j<16;j++) se += __expf(v[j]-m);
                float logZ = m + logf(se);
                float tg = clampf(tgt[s], 0.f, 14.99f);
                int   tl = (int)tg;
                float wl = (float)(tl+1) - tg;
                float ce_l = logZ - v[tl];
                float ce_r = logZ - v[tl+1];
                dfl += ce_l*wl + ce_r*(1.f-wl);
            }
            accDfl = (double)(w * (dfl * 0.25f));
        }
        // ---- aspect-ratio prior loss ----
        if (fg){
            float gwc = fmaxf(tbx2-tbx1, 1e-4f);
            float ghc = fmaxf(tby2-tby1, 1e-4f);
            if (ghc/gwc >= 1.2f){
                float pwc = fmaxf(px2-px1, 1e-4f);
                float phc = fmaxf(py2-py1, 1e-4f);
                float pen = fmaxf(1.5f - phc/pwc, 0.f) * (1.f - clampf(maxIou,0.f,1.f));
                accAsp  = (double)pen;
                accGate = 1.0;
            }
        }
    }

    // deterministic block reduction of 6 accumulators
    double vals[6] = {accCls, accBox, accDfl, accAsp, accTss, accGate};
    int part = blockIdx.y*MAIN_BX + blockIdx.x;
    #pragma unroll
    for (int k=0;k<6;k++){
        rd[tid] = vals[k];
        __syncthreads();
        for (int s=128; s>0; s>>=1){
            if (tid < s) rd[tid] += rd[tid+s];
            __syncthreads();
        }
        if (tid == 0) g_part[part*6+k] = rd[0];
        __syncthreads();
    }
}

// ---------------- Final: deterministic global reduce + loss combine ----------------
__global__ void k_final(float* __restrict__ out){
    __shared__ double rd[256];
    int tid = threadIdx.x;
    double v[6] = {0,0,0,0,0,0};
    for (int i=tid; i<NPART; i+=256){
        #pragma unroll
        for (int k=0;k<6;k++) v[k] += g_part[i*6+k];
    }
    double tot[6];
    #pragma unroll
    for (int k=0;k<6;k++){
        rd[tid] = v[k];
        __syncthreads();
        for (int s=128; s>0; s>>=1){
            if (tid < s) rd[tid] += rd[tid+s];
            __syncthreads();
        }
        tot[k] = rd[0];
        __syncthreads();
    }
    if (tid == 0){
        double tss = tot[4] > 1.0 ? tot[4] : 1.0;
        double gc  = tot[5] > 1.0 ? tot[5] : 1.0;
        double total = 7.5*(tot[1]/tss) + 0.5*(tot[0]/tss) + 1.5*(tot[2]/tss) + 0.1*(tot[3]/gc);
        out[0] = (float)total;
    }
}

extern "C" void kernel_launch(void* const* d_in, const int* in_sizes, int n_in,
                              void* d_out, int out_size){
    (void)in_sizes; (void)n_in; (void)out_size;
    const float* cls = (const float*)d_in[0];   // [B,A,NC]
    const float* pdist = (const float*)d_in[1]; // [B,A,4,16]
    const float* anc = (const float*)d_in[2];   // [A,2]
    const float* str = (const float*)d_in[3];   // [A,1]
    const float* gtb = (const float*)d_in[4];   // [B,G,4]
    const int*   gtl = (const int*)d_in[5];     // [B,G]

    k_decode<<<(NB*NA+255)/256, 256>>>(pdist, anc, str);
    k_sqcls<<<dim3(NA/40, NB), 800>>>(cls);
    k_align<<<dim3(NG, NB), 256>>>(anc, str, gtb, gtl);
    k_main<<<dim3(MAIN_BX, NB), 256>>>(cls, pdist, anc, str, gtb, gtl);
    k_final<<<1, 256>>>((float*)d_out);
}

// round 2
// speedup vs baseline: 3.1580x; 3.1580x over previous
#include <cuda_runtime.h>
#include <math.h>
#include <float.h>

// Problem constants (fixed by reference setup)
#define NB    32
#define NA    8400
#define NCLS  20
#define NG    128
#define NTOPK 10
#define MAIN_BX 33                 // ceil(8400/256)
#define NPART (MAIN_BX*NB)

// ---- static scratch (no allocations allowed) ----
static __device__ float  g_pred[(size_t)NB*NA*4];   // pred_xyxy px (4.3 MB)
static __device__ float  g_thresh[NB*NG];           // per-gt topk threshold
static __device__ double g_part[NPART*6];           // block partials

__device__ __forceinline__ float clampf(float x, float lo, float hi){ return fminf(fmaxf(x,lo),hi); }

// align value; MUST be the single shared definition used by both passes so
// threshold comparisons are bit-identical.
__device__ __forceinline__ float align_core(float sq,
                                            float px1,float py1,float px2,float py2,
                                            float gx1,float gy1,float gx2,float gy2,float ga){
    float iw = fminf(px2,gx2)-fmaxf(px1,gx1); iw=fmaxf(iw,0.f);
    float ih = fminf(py2,gy2)-fmaxf(py1,gy1); ih=fmaxf(ih,0.f);
    float inter = iw*ih;
    float pa = fmaxf((px2-px1)*(py2-py1),0.f);
    float iou = inter/(pa+ga-inter+1e-7f);
    iou = clampf(iou,0.f,1.f);
    float i2=iou*iou;
    return sq*(i2*i2*i2);
}

__device__ __forceinline__ float pair_iou(float px1,float py1,float px2,float py2,
                                          float tx1,float ty1,float tx2,float ty2){
    float iw = fminf(px2,tx2) - fmaxf(px1,tx1); iw = fmaxf(iw, 0.f);
    float ih = fminf(py2,ty2) - fmaxf(py1,ty1); ih = fmaxf(ih, 0.f);
    float inter = iw*ih;
    float pa = fmaxf((px2-px1)*(py2-py1), 0.f);
    float ta = fmaxf((tx2-tx1)*(ty2-ty1), 0.f);
    return inter / (pa + ta - inter + 1e-7f);
}

__device__ __forceinline__ float ciou_loss(float px1,float py1,float px2,float py2,
                                           float tx1,float ty1,float tx2,float ty2){
    const float eps = 1e-7f;
    float iw = fminf(px2,tx2) - fmaxf(px1,tx1); iw = fmaxf(iw,0.f);
    float ih = fminf(py2,ty2) - fmaxf(py1,ty1); ih = fmaxf(ih,0.f);
    float inter = iw*ih;
    float pw = fmaxf(px2-px1,0.f), ph = fmaxf(py2-py1,0.f);
    float tw = fmaxf(tx2-tx1,0.f), th = fmaxf(ty2-ty1,0.f);
    float uni = pw*ph + tw*th - inter + eps;
    float iou = inter/uni;
    float dx = (px1+px2)*0.5f - (tx1+tx2)*0.5f;
    float dy = (py1+py2)*0.5f - (ty1+ty2)*0.5f;
    float d2 = dx*dx + dy*dy;
    float ew = fmaxf(fmaxf(px2,tx2)-fminf(px1,tx1),0.f);
    float eh = fmaxf(fmaxf(py2,ty2)-fminf(py1,ty1),0.f);
    float c2 = ew*ew + eh*eh + eps;
    float da = atanf(tw/(th+eps)) - atanf(pw/(ph+eps));
    float v  = 0.40528473456935108577f * da*da;   // 4/pi^2
    float av = v / (1.f - iou + v + eps);
    return 1.f - (iou - d2/c2 - av*v);
}

// ---------------- Stage A: DFL decode -> pred boxes (px) ----------------
__global__ void k_decode(const float* __restrict__ pd,
                         const float* __restrict__ anc,
                         const float* __restrict__ str){
    int i = blockIdx.x*blockDim.x + threadIdx.x;
    if (i >= NB*NA) return;
    int a = i % NA;
    const float4* x4 = reinterpret_cast<const float4*>(pd + (size_t)i*64);
    float d[4];
    #pragma unroll
    for (int s=0;s<4;s++){
        float v[16];
        #pragma unroll
        for (int q=0;q<4;q++){
            float4 f = x4[s*4+q];
            v[q*4+0]=f.x; v[q*4+1]=f.y; v[q*4+2]=f.z; v[q*4+3]=f.w;
        }
        float m = v[0];
        #pragma unroll
        for (int j=1;j<16;j++) m = fmaxf(m, v[j]);
        float se=0.f, sw=0.f;
        #pragma unroll
        for (int j=0;j<16;j++){ float e=__expf(v[j]-m); se+=e; sw+=e*(float)j; }
        d[s] = sw/se;
    }
    float ax = anc[2*a], ay = anc[2*a+1], st = str[a];
    float* o = g_pred + (size_t)i*4;
    o[0]=(ax-d[0])*st; o[1]=(ay-d[1])*st; o[2]=(ax+d[2])*st; o[3]=(ay+d[3])*st;
}

// ---------------- Stage B: per-gt topk threshold via rectangle enumeration ----------------
__global__ void k_thresh(const float* __restrict__ cls,
                         const float* __restrict__ gtb,
                         const int*   __restrict__ gtl){
    __shared__ float s_val[1312];
    __shared__ int s_cnt;
    int b = blockIdx.y, g = blockIdx.x, tid = threadIdx.x;
    int lbl = gtl[b*NG+g];
    if (lbl < 0){ if (tid==0) g_thresh[b*NG+g] = 0.f; return; }
    int lc = lbl > NCLS-1 ? NCLS-1 : lbl;
    float4 gb = *reinterpret_cast<const float4*>(gtb + ((size_t)(b*NG+g))*4);
    float gx1=gb.x, gy1=gb.y, gx2=gb.z, gy2=gb.w;
    float ga = fmaxf((gx2-gx1)*(gy2-gy1), 0.f);
    if (tid==0) s_cnt=0;
    __syncthreads();
    const float* pr = g_pred + (size_t)b*NA*4;
    const float* cl = cls + (size_t)b*NA*NCLS;
    const int soff[3] = {0, 6400, 8000};
    const int sn[3]   = {80, 40, 20};
    const float sfv[3]= {8.f, 16.f, 32.f};
    #pragma unroll
    for (int si=0; si<3; si++){
        float s = sfv[si]; int n = sn[si];
        int ix0 = (int)floorf(gx1/s - 0.5f) - 1; if (ix0 < 0)   ix0 = 0;
        int ix1 = (int)ceilf (gx2/s - 0.5f) + 1; if (ix1 > n-1) ix1 = n-1;
        int iy0 = (int)floorf(gy1/s - 0.5f) - 1; if (iy0 < 0)   iy0 = 0;
        int iy1 = (int)ceilf (gy2/s - 0.5f) + 1; if (iy1 > n-1) iy1 = n-1;
        int w = ix1-ix0+1, h = iy1-iy0+1;
        if (w <= 0 || h <= 0) continue;
        int cells = w*h;
        for (int c = tid; c < cells; c += 256){
            int ix = ix0 + c % w;
            int iy = iy0 + c / w;
            float ax = ((float)ix + 0.5f)*s;     // exact, same bits as anc*str
            float ay = ((float)iy + 0.5f)*s;
            if (ax>gx1 && ax<gx2 && ay>gy1 && ay<gy2){
                int a = soff[si] + iy*n + ix;
                float4 p = *reinterpret_cast<const float4*>(pr + (size_t)a*4);
                float sq = sqrtf(clampf(cl[(size_t)a*NCLS + lc], 0.f, 1.f));
                float al = align_core(sq, p.x,p.y,p.z,p.w, gx1,gy1,gx2,gy2, ga);
                int idx = atomicAdd(&s_cnt, 1);
                if (idx < 1312) s_val[idx] = al;
            }
        }
    }
    __syncthreads();
    int m = s_cnt; if (m > 1312) m = 1312;
    if (tid < 32){
        float th = 0.f;
        if (m >= NTOPK){
            float t = FLT_MAX;
            #pragma unroll 1
            for (int iter=0; iter<NTOPK; iter++){
                float mx = -1.f;
                for (int j=tid; j<m; j+=32){
                    float v = s_val[j];
                    if (v < t && v > mx) mx = v;
                }
                #pragma unroll
                for (int o=16;o;o>>=1) mx = fmaxf(mx, __shfl_xor_sync(0xffffffffu, mx, o));
                int c = 0;
                for (int j=tid; j<m; j+=32) c += (s_val[j] >= mx);
                #pragma unroll
                for (int o=16;o;o>>=1) c += __shfl_xor_sync(0xffffffffu, c, o);
                th = mx;
                if (c >= NTOPK) break;
                t = mx;
            }
        }
        if (tid==0) g_thresh[b*NG+g] = th;
    }
}

// ---------------- Stage C: per-anchor assignment + fused losses ----------------
__global__ void k_main(const float* __restrict__ cls,
                       const float* __restrict__ pd,
                       const float* __restrict__ anc,
                       const float* __restrict__ str,
                       const float* __restrict__ gtb,
                       const int*   __restrict__ gtl){
    __shared__ float  s_cls[256*21];    // raw cls per thread, pitch 21 (conflict-free)
    __shared__ float4 s_cgt[NG];        // compacted gt boxes (ascending g order)
    __shared__ float  s_cth[NG];
    __shared__ int    s_clbl[NG];
    __shared__ float  s_f[32];
    __shared__ int    s_wcnt[8];
    __shared__ int    s_M;
    __shared__ double s_ws[8*6];
    __shared__ float  s_bb[4];

    int b = blockIdx.y, tid = threadIdx.x;
    int a = blockIdx.x*256 + tid;
    bool act = a < NA;
    int lane = tid & 31, wid = tid >> 5;

    float st=8.f, ax=0.f, ay=0.f;
    float px1=0.f,py1=0.f,px2=0.f,py2=0.f;
    float sumLg = 0.f;                  // sum of log(1-p) over all classes
    if (act){
        st = str[a];
        ax = anc[2*a]*st; ay = anc[2*a+1]*st;
        float4 p = *reinterpret_cast<const float4*>(g_pred + ((size_t)b*NA+a)*4);
        px1=p.x; py1=p.y; px2=p.z; py2=p.w;
        const float4* cp4 = reinterpret_cast<const float4*>(cls + ((size_t)b*NA+a)*NCLS);
        #pragma unroll
        for (int q=0;q<5;q++){
            float4 f = cp4[q];
            float e0=f.x, e1=f.y, e2=f.z, e3=f.w;
            s_cls[tid*21+q*4+0]=e0; s_cls[tid*21+q*4+1]=e1;
            s_cls[tid*21+q*4+2]=e2; s_cls[tid*21+q*4+3]=e3;
            sumLg += logf(1.f - clampf(e0,1e-7f,1.f-1e-7f));
            sumLg += logf(1.f - clampf(e1,1e-7f,1.f-1e-7f));
            sumLg += logf(1.f - clampf(e2,1e-7f,1.f-1e-7f));
            sumLg += logf(1.f - clampf(e3,1e-7f,1.f-1e-7f));
        }
    }

    // block bbox of active anchor centers
    float axm = act?ax: FLT_MAX, axM = act?ax:-FLT_MAX;
    float aym = act?ay: FLT_MAX, ayM = act?ay:-FLT_MAX;
    #pragma unroll
    for (int o=16;o;o>>=1){
        axm = fminf(axm, __shfl_xor_sync(0xffffffffu, axm, o));
        axM = fmaxf(axM, __shfl_xor_sync(0xffffffffu, axM, o));
        aym = fminf(aym, __shfl_xor_sync(0xffffffffu, aym, o));
        ayM = fmaxf(ayM, __shfl_xor_sync(0xffffffffu, ayM, o));
    }
    if (lane==0){ s_f[wid]=axm; s_f[8+wid]=axM; s_f[16+wid]=aym; s_f[24+wid]=ayM; }
    __syncthreads();
    if (tid==0){
        float a0=FLT_MAX,a1=-FLT_MAX,a2=FLT_MAX,a3=-FLT_MAX;
        #pragma unroll
        for (int wq=0;wq<8;wq++){
            a0=fminf(a0,s_f[wq]);    a1=fmaxf(a1,s_f[8+wq]);
            a2=fminf(a2,s_f[16+wq]); a3=fmaxf(a3,s_f[24+wq]);
        }
        s_bb[0]=a0; s_bb[1]=a1; s_bb[2]=a2; s_bb[3]=a3;
    }
    __syncthreads();
    float bxm=s_bb[0], bxM=s_bb[1], bym=s_bb[2], byM=s_bb[3];

    // ordered compaction of candidate gts (tid<128 tests gt=tid)
    bool ok = false; int l = 0; float4 gq4 = make_float4(0,0,0,0); float thv = 0.f;
    if (tid < 128){
        l = gtl[b*NG+tid];
        gq4 = *reinterpret_cast<const float4*>(gtb + ((size_t)(b*NG+tid))*4);
        thv = g_thresh[b*NG+tid];
        ok = (l >= 0) && (gq4.x < bxM) && (gq4.z > bxm) && (gq4.y < byM) && (gq4.w > bym);
    }
    unsigned bal = __ballot_sync(0xffffffffu, ok);
    int pre = __popc(bal & ((1u<<lane)-1u));
    if (lane==0) s_wcnt[wid] = __popc(bal);
    __syncthreads();
    if (tid==0){
        int tot=0;
        #pragma unroll
        for (int wq=0;wq<8;wq++){ int c=s_wcnt[wq]; s_wcnt[wq]=tot; tot+=c; }
        s_M = tot;
    }
    __syncthreads();
    if (ok){
        int pos = s_wcnt[wid] + pre;
        s_cgt[pos] = gq4;
        s_cth[pos] = thv;
        s_clbl[pos] = (l > NCLS-1) ? NCLS-1 : l;
    }
    __syncthreads();
    int M = s_M;

    // main assignment loop over compacted gts
    float bestV = -1.f; int bestJ = 0, firstJ = 0; int claims = 0;
    if (act){
        for (int j=0; j<M; j++){
            float4 gq = s_cgt[j];
            if (ax>gq.x && ax<gq.z && ay>gq.y && ay<gq.w){
                float ga = fmaxf((gq.z-gq.x)*(gq.w-gq.y), 0.f);
                float sq = sqrtf(clampf(s_cls[tid*21 + s_clbl[j]], 0.f, 1.f));
                float al = align_core(sq, px1,py1,px2,py2, gq.x,gq.y,gq.z,gq.w, ga);
                if (al > bestV){ bestV=al; bestJ=j; }
                if (al >= s_cth[j]){ if (claims==0) firstJ=j; claims++; }
            }
        }
    }

    double acc0=0.0, acc1=0.0, acc2=0.0, acc3=0.0, acc4=0.0, acc5=0.0;
    if (act){
        bool fg = claims > 0;
        int jA = (claims > 1) ? bestJ : firstJ;
        float tbx1=0.f,tby1=0.f,tbx2=0.f,tby2=0.f, maxIou=0.f; int pl=0;
        if (fg){
            float4 t4 = s_cgt[jA];
            tbx1=t4.x; tby1=t4.y; tbx2=t4.z; tby2=t4.w;
            pl = s_clbl[jA];
            maxIou = pair_iou(px1,py1,px2,py2, tbx1,tby1,tbx2,tby2);
        }
        float alMax = fmaxf(bestV, 0.f);
        float soft  = alMax * maxIou / fmaxf(alMax, 1e-9f);
        float w     = fg ? soft : 0.f;
        acc4 = (double)w;

        // classification BCE: background sum + target-class correction
        acc0 = -(double)sumLg;
        if (w > 0.f){
            float pc = clampf(s_cls[tid*21+pl], 1e-7f, 1.f-1e-7f);
            acc0 += (double)(w * (logf(1.f-pc) - logf(pc)));
            // CIoU box loss
            acc1 = (double)(w * ciou_loss(px1,py1,px2,py2, tbx1,tby1,tbx2,tby2));
            // DFL loss
            float tgt[4];
            tgt[0] = (ax - tbx1)/st;
            tgt[1] = (ay - tby1)/st;
            tgt[2] = (tbx2 - ax)/st;
            tgt[3] = (tby2 - ay)/st;
            const float4* x4 = reinterpret_cast<const float4*>(pd + ((size_t)b*NA + a)*64);
            float dfl = 0.f;
            #pragma unroll
            for (int s=0;s<4;s++){
                float v[16];
                #pragma unroll
                for (int q=0;q<4;q++){
                    float4 f = x4[s*4+q];
                    v[q*4+0]=f.x; v[q*4+1]=f.y; v[q*4+2]=f.z; v[q*4+3]=f.w;
                }
                float m = v[0];
                #pragma unroll
                for (int j=1;j<16;j++) m = fmaxf(m, v[j]);
                float se = 0.f;
                #pragma unroll
                for (int j=0;j<16;j++) se += __expf(v[j]-m);
                float logZ = m + logf(se);
                float tg = clampf(tgt[s], 0.f, 14.99f);
                int   tl = (int)tg;
                float wl = (float)(tl+1) - tg;
                dfl += (logZ - v[tl])*wl + (logZ - v[tl+1])*(1.f-wl);
            }
            acc2 = (double)(w * (dfl * 0.25f));
        }
        // aspect-ratio prior loss
        if (fg){
            float gwc = fmaxf(tbx2-tbx1, 1e-4f);
            float ghc = fmaxf(tby2-tby1, 1e-4f);
            if (ghc/gwc >= 1.2f){
                float pwc = fmaxf(px2-px1, 1e-4f);
                float phc = fmaxf(py2-py1, 1e-4f);
                float pen = fmaxf(1.5f - phc/pwc, 0.f) * (1.f - clampf(maxIou,0.f,1.f));
                acc3 = (double)pen;
                acc5 = 1.0;
            }
        }
    }

    // deterministic reduction: warp shfl then per-warp partials
    double accs[6] = {acc0, acc1, acc2, acc3, acc4, acc5};
    #pragma unroll
    for (int k=0;k<6;k++){
        double v = accs[k];
        #pragma unroll
        for (int o=16;o;o>>=1) v += __shfl_down_sync(0xffffffffu, v, o);
        if (lane==0) s_ws[wid*6+k] = v;
    }
    __syncthreads();
    if (tid < 6){
        double v = 0.0;
        #pragma unroll
        for (int wq=0;wq<8;wq++) v += s_ws[wq*6+tid];
        int part = blockIdx.y*MAIN_BX + blockIdx.x;
        g_part[part*6+tid] = v;
    }
}

// ---------------- Final: deterministic global reduce + loss combine ----------------
__global__ void k_final(float* __restrict__ out){
    __shared__ double rd[256];
    int tid = threadIdx.x;
    double v[6] = {0,0,0,0,0,0};
    for (int i=tid; i<NPART; i+=256){
        #pragma unroll
        for (int k=0;k<6;k++) v[k] += g_part[i*6+k];
    }
    double tot[6];
    #pragma unroll
    for (int k=0;k<6;k++){
        rd[tid] = v[k];
        __syncthreads();
        for (int s=128; s>0; s>>=1){
            if (tid < s) rd[tid] += rd[tid+s];
            __syncthreads();
        }
        tot[k] = rd[0];
        __syncthreads();
    }
    if (tid == 0){
        double tss = tot[4] > 1.0 ? tot[4] : 1.0;
        double gc  = tot[5] > 1.0 ? tot[5] : 1.0;
        double total = 7.5*(tot[1]/tss) + 0.5*(tot[0]/tss) + 1.5*(tot[2]/tss) + 0.1*(tot[3]/gc);
        out[0] = (float)total;
    }
}

extern "C" void kernel_launch(void* const* d_in, const int* in_sizes, int n_in,
                              void* d_out, int out_size){
    (void)in_sizes; (void)n_in; (void)out_size;
    const float* cls   = (const float*)d_in[0];   // [B,A,NC]
    const float* pdist = (const float*)d_in[1];   // [B,A,4,16]
    const float* anc   = (const float*)d_in[2];   // [A,2]
    const float* str   = (const float*)d_in[3];   // [A,1]
    const float* gtb   = (const float*)d_in[4];   // [B,G,4]
    const int*   gtl   = (const int*)d_in[5];     // [B,G]

    k_decode<<<(NB*NA+255)/256, 256>>>(pdist, anc, str);
    k_thresh<<<dim3(NG, NB), 256>>>(cls, gtb, gtl);
    k_main  <<<dim3(MAIN_BX, NB), 256>>>(cls, pdist, anc, str, gtb, gtl);
    k_final <<<1, 256>>>((float*)d_out);
}

// round 3
// speedup vs baseline: 3.1603x; 1.0007x over previous
#include <cuda_runtime.h>
#include <math.h>
#include <float.h>

// Problem constants (fixed by reference setup)
#define NB    32
#define NA    8400
#define NCLS  20
#define NG    128
#define NTOPK 10
#define MAIN_BX 33                 // ceil(8400/256)
#define NPART (MAIN_BX*NB)

// ---- static scratch (no allocations allowed) ----
static __device__ float  g_pred[(size_t)NB*NA*4];   // pred_xyxy px (4.3 MB)
static __device__ float  g_thresh[NB*NG];           // per-gt topk threshold
static __device__ double g_part[NPART*6];           // block partials
static __device__ unsigned int g_done = 0;          // completion counter (self-resetting)

__device__ __forceinline__ float clampf(float x, float lo, float hi){ return fminf(fmaxf(x,lo),hi); }

// align value; MUST be the single shared definition used by both passes so
// threshold comparisons are bit-identical.
__device__ __forceinline__ float align_core(float sq,
                                            float px1,float py1,float px2,float py2,
                                            float gx1,float gy1,float gx2,float gy2,float ga){
    float iw = fminf(px2,gx2)-fmaxf(px1,gx1); iw=fmaxf(iw,0.f);
    float ih = fminf(py2,gy2)-fmaxf(py1,gy1); ih=fmaxf(ih,0.f);
    float inter = iw*ih;
    float pa = fmaxf((px2-px1)*(py2-py1),0.f);
    float iou = inter/(pa+ga-inter+1e-7f);
    iou = clampf(iou,0.f,1.f);
    float i2=iou*iou;
    return sq*(i2*i2*i2);
}

__device__ __forceinline__ float pair_iou(float px1,float py1,float px2,float py2,
                                          float tx1,float ty1,float tx2,float ty2){
    float iw = fminf(px2,tx2) - fmaxf(px1,tx1); iw = fmaxf(iw, 0.f);
    float ih = fminf(py2,ty2) - fmaxf(py1,ty1); ih = fmaxf(ih, 0.f);
    float inter = iw*ih;
    float pa = fmaxf((px2-px1)*(py2-py1), 0.f);
    float ta = fmaxf((tx2-tx1)*(ty2-ty1), 0.f);
    return inter / (pa + ta - inter + 1e-7f);
}

__device__ __forceinline__ float ciou_loss(float px1,float py1,float px2,float py2,
                                           float tx1,float ty1,float tx2,float ty2){
    const float eps = 1e-7f;
    float iw = fminf(px2,tx2) - fmaxf(px1,tx1); iw = fmaxf(iw,0.f);
    float ih = fminf(py2,ty2) - fmaxf(py1,ty1); ih = fmaxf(ih,0.f);
    float inter = iw*ih;
    float pw = fmaxf(px2-px1,0.f), ph = fmaxf(py2-py1,0.f);
    float tw = fmaxf(tx2-tx1,0.f), th = fmaxf(ty2-ty1,0.f);
    float uni = pw*ph + tw*th - inter + eps;
    float iou = inter/uni;
    float dx = (px1+px2)*0.5f - (tx1+tx2)*0.5f;
    float dy = (py1+py2)*0.5f - (ty1+ty2)*0.5f;
    float d2 = dx*dx + dy*dy;
    float ew = fmaxf(fmaxf(px2,tx2)-fminf(px1,tx1),0.f);
    float eh = fmaxf(fmaxf(py2,ty2)-fminf(py1,ty1),0.f);
    float c2 = ew*ew + eh*eh + eps;
    float da = atanf(tw/(th+eps)) - atanf(pw/(ph+eps));
    float v  = 0.40528473456935108577f * da*da;   // 4/pi^2
    float av = v / (1.f - iou + v + eps);
    return 1.f - (iou - d2/c2 - av*v);
}

// ---------------- Stage A: DFL decode -> pred boxes (px) ----------------
__global__ void k_decode(const float* __restrict__ pd,
                         const float* __restrict__ anc,
                         const float* __restrict__ str){
    int i = blockIdx.x*blockDim.x + threadIdx.x;
    if (i >= NB*NA) return;
    int a = i % NA;
    const float4* x4 = reinterpret_cast<const float4*>(pd + (size_t)i*64);
    float d[4];
    #pragma unroll
    for (int s=0;s<4;s++){
        float v[16];
        #pragma unroll
        for (int q=0;q<4;q++){
            float4 f = x4[s*4+q];
            v[q*4+0]=f.x; v[q*4+1]=f.y; v[q*4+2]=f.z; v[q*4+3]=f.w;
        }
        float m = v[0];
        #pragma unroll
        for (int j=1;j<16;j++) m = fmaxf(m, v[j]);
        float se=0.f, sw=0.f;
        #pragma unroll
        for (int j=0;j<16;j++){ float e=__expf(v[j]-m); se+=e; sw+=e*(float)j; }
        d[s] = sw/se;
    }
    float ax = anc[2*a], ay = anc[2*a+1], st = str[a];
    float* o = g_pred + (size_t)i*4;
    o[0]=(ax-d[0])*st; o[1]=(ay-d[1])*st; o[2]=(ax+d[2])*st; o[3]=(ay+d[3])*st;
}

// ---------------- Stage B: per-gt topk threshold via rectangle enumeration ----------------
__global__ void k_thresh(const float* __restrict__ cls,
                         const float* __restrict__ gtb,
                         const int*   __restrict__ gtl){
    __shared__ float s_val[1312];
    __shared__ int s_cnt;
    int b = blockIdx.y, g = blockIdx.x, tid = threadIdx.x;
    int lane = tid & 31;
    int lbl = gtl[b*NG+g];
    if (lbl < 0){ if (tid==0) g_thresh[b*NG+g] = 0.f; return; }
    int lc = lbl > NCLS-1 ? NCLS-1 : lbl;
    float4 gb = *reinterpret_cast<const float4*>(gtb + ((size_t)(b*NG+g))*4);
    float gx1=gb.x, gy1=gb.y, gx2=gb.z, gy2=gb.w;
    float ga = fmaxf((gx2-gx1)*(gy2-gy1), 0.f);
    if (tid==0) s_cnt=0;
    __syncthreads();
    const float* pr = g_pred + (size_t)b*NA*4;
    const float* cl = cls + (size_t)b*NA*NCLS;
    const int soff[3] = {0, 6400, 8000};
    const int sn[3]   = {80, 40, 20};
    const float sfv[3]= {8.f, 16.f, 32.f};
    #pragma unroll
    for (int si=0; si<3; si++){
        float s = sfv[si]; int n = sn[si];
        int ix0 = (int)floorf(gx1/s - 0.5f) - 1; if (ix0 < 0)   ix0 = 0;
        int ix1 = (int)ceilf (gx2/s - 0.5f) + 1; if (ix1 > n-1) ix1 = n-1;
        int iy0 = (int)floorf(gy1/s - 0.5f) - 1; if (iy0 < 0)   iy0 = 0;
        int iy1 = (int)ceilf (gy2/s - 0.5f) + 1; if (iy1 > n-1) iy1 = n-1;
        int w = ix1-ix0+1, h = iy1-iy0+1;
        if (w <= 0 || h <= 0) continue;
        int cells = w*h;
        int iters = (cells + 255) / 256;
        for (int it = 0; it < iters; it++){
            int c = it*256 + tid;
            bool inbox = false;
            float al = 0.f;
            if (c < cells){
                int ix = ix0 + c % w;
                int iy = iy0 + c / w;
                float ax = ((float)ix + 0.5f)*s;   // exact, same bits as anc*str
                float ay = ((float)iy + 0.5f)*s;
                if (ax>gx1 && ax<gx2 && ay>gy1 && ay<gy2){
                    int a = soff[si] + iy*n + ix;
                    float4 p = *reinterpret_cast<const float4*>(pr + (size_t)a*4);
                    float sq = sqrtf(clampf(cl[(size_t)a*NCLS + lc], 0.f, 1.f));
                    al = align_core(sq, p.x,p.y,p.z,p.w, gx1,gy1,gx2,gy2, ga);
                    inbox = true;
                }
            }
            // warp-aggregated append
            unsigned msk = __ballot_sync(0xffffffffu, inbox);
            int base = 0;
            if (lane == __ffs(msk|0x80000000u)-1 && msk)   // leader = lowest set lane
                base = atomicAdd(&s_cnt, __popc(msk));
            base = __shfl_sync(0xffffffffu, base, msk ? (__ffs(msk)-1) : 0);
            if (inbox){
                int idx = base + __popc(msk & ((1u<<lane)-1u));
                if (idx < 1312) s_val[idx] = al;
            }
        }
    }
    __syncthreads();
    int m = s_cnt; if (m > 1312) m = 1312;
    if (tid < 32){
        float th = 0.f;
        if (m >= NTOPK){
            float t = FLT_MAX;
            #pragma unroll 1
            for (int iter=0; iter<NTOPK; iter++){
                float mx = -1.f;
                for (int j=tid; j<m; j+=32){
                    float v = s_val[j];
                    if (v < t && v > mx) mx = v;
                }
                #pragma unroll
                for (int o=16;o;o>>=1) mx = fmaxf(mx, __shfl_xor_sync(0xffffffffu, mx, o));
                int c = 0;
                for (int j=tid; j<m; j+=32) c += (s_val[j] >= mx);
                #pragma unroll
                for (int o=16;o;o>>=1) c += __shfl_xor_sync(0xffffffffu, c, o);
                th = mx;
                if (c >= NTOPK) break;
                t = mx;
            }
        }
        if (tid==0) g_thresh[b*NG+g] = th;
    }
}

// ---------------- Stage C: per-anchor assignment + fused losses + final combine ----------------
__global__ void k_main(const float* __restrict__ cls,
                       const float* __restrict__ pd,
                       const float* __restrict__ anc,
                       const float* __restrict__ str,
                       const float* __restrict__ gtb,
                       const int*   __restrict__ gtl,
                       float* __restrict__ out){
    __shared__ float  s_cls[256*21];    // raw cls per thread, pitch 21 (conflict-free)
    __shared__ float4 s_cgt[NG];        // compacted gt boxes (ascending g order)
    __shared__ float  s_cth[NG];
    __shared__ int    s_clbl[NG];
    __shared__ float  s_f[32];
    __shared__ int    s_wcnt[8];
    __shared__ int    s_M;
    __shared__ double s_ws[8*6];
    __shared__ float  s_bb[4];
    __shared__ int    s_last;

    int b = blockIdx.y, tid = threadIdx.x;
    int a = blockIdx.x*256 + tid;
    bool act = a < NA;
    int lane = tid & 31, wid = tid >> 5;

    float st=8.f, ax=0.f, ay=0.f;
    float px1=0.f,py1=0.f,px2=0.f,py2=0.f;
    float sumLg = 0.f;                  // sum of log(1-p) over all classes
    if (act){
        st = str[a];
        ax = anc[2*a]*st; ay = anc[2*a+1]*st;
        float4 p = *reinterpret_cast<const float4*>(g_pred + ((size_t)b*NA+a)*4);
        px1=p.x; py1=p.y; px2=p.z; py2=p.w;
        const float4* cp4 = reinterpret_cast<const float4*>(cls + ((size_t)b*NA+a)*NCLS);
        #pragma unroll
        for (int q=0;q<5;q++){
            float4 f = cp4[q];
            s_cls[tid*21+q*4+0]=f.x; s_cls[tid*21+q*4+1]=f.y;
            s_cls[tid*21+q*4+2]=f.z; s_cls[tid*21+q*4+3]=f.w;
            // grouped: log((1-a)(1-b)(1-c)(1-d)); each factor >= 1e-7 => prod >= 1e-28
            float g0 = 1.f - clampf(f.x,1e-7f,1.f-1e-7f);
            float g1 = 1.f - clampf(f.y,1e-7f,1.f-1e-7f);
            float g2 = 1.f - clampf(f.z,1e-7f,1.f-1e-7f);
            float g3 = 1.f - clampf(f.w,1e-7f,1.f-1e-7f);
            sumLg += __logf((g0*g1)*(g2*g3));
        }
    }

    // block bbox of active anchor centers
    float axm = act?ax: FLT_MAX, axM = act?ax:-FLT_MAX;
    float aym = act?ay: FLT_MAX, ayM = act?ay:-FLT_MAX;
    #pragma unroll
    for (int o=16;o;o>>=1){
        axm = fminf(axm, __shfl_xor_sync(0xffffffffu, axm, o));
        axM = fmaxf(axM, __shfl_xor_sync(0xffffffffu, axM, o));
        aym = fminf(aym, __shfl_xor_sync(0xffffffffu, aym, o));
        ayM = fmaxf(ayM, __shfl_xor_sync(0xffffffffu, ayM, o));
    }
    if (lane==0){ s_f[wid]=axm; s_f[8+wid]=axM; s_f[16+wid]=aym; s_f[24+wid]=ayM; }
    __syncthreads();
    if (tid==0){
        float a0=FLT_MAX,a1=-FLT_MAX,a2=FLT_MAX,a3=-FLT_MAX;
        #pragma unroll
        for (int wq=0;wq<8;wq++){
            a0=fminf(a0,s_f[wq]);    a1=fmaxf(a1,s_f[8+wq]);
            a2=fminf(a2,s_f[16+wq]); a3=fmaxf(a3,s_f[24+wq]);
        }
        s_bb[0]=a0; s_bb[1]=a1; s_bb[2]=a2; s_bb[3]=a3;
    }
    __syncthreads();
    float bxm=s_bb[0], bxM=s_bb[1], bym=s_bb[2], byM=s_bb[3];

    // ordered compaction of candidate gts (tid<128 tests gt=tid)
    bool ok = false; int l = 0; float4 gq4 = make_float4(0,0,0,0); float thv = 0.f;
    if (tid < 128){
        l = gtl[b*NG+tid];
        gq4 = *reinterpret_cast<const float4*>(gtb + ((size_t)(b*NG+tid))*4);
        thv = g_thresh[b*NG+tid];
        ok = (l >= 0) && (gq4.x < bxM) && (gq4.z > bxm) && (gq4.y < byM) && (gq4.w > bym);
    }
    unsigned bal = __ballot_sync(0xffffffffu, ok);
    int pre = __popc(bal & ((1u<<lane)-1u));
    if (lane==0) s_wcnt[wid] = __popc(bal);
    __syncthreads();
    if (tid==0){
        int tot=0;
        #pragma unroll
        for (int wq=0;wq<8;wq++){ int c=s_wcnt[wq]; s_wcnt[wq]=tot; tot+=c; }
        s_M = tot;
    }
    __syncthreads();
    if (ok){
        int pos = s_wcnt[wid] + pre;
        s_cgt[pos] = gq4;
        s_cth[pos] = thv;
        s_clbl[pos] = (l > NCLS-1) ? NCLS-1 : l;
    }
    __syncthreads();
    int M = s_M;

    // main assignment loop over compacted gts
    float bestV = -1.f; int bestJ = 0, firstJ = 0; int claims = 0;
    if (act){
        for (int j=0; j<M; j++){
            float4 gq = s_cgt[j];
            if (ax>gq.x && ax<gq.z && ay>gq.y && ay<gq.w){
                float ga = fmaxf((gq.z-gq.x)*(gq.w-gq.y), 0.f);
                float sq = sqrtf(clampf(s_cls[tid*21 + s_clbl[j]], 0.f, 1.f));
                float al = align_core(sq, px1,py1,px2,py2, gq.x,gq.y,gq.z,gq.w, ga);
                if (al > bestV){ bestV=al; bestJ=j; }
                if (al >= s_cth[j]){ if (claims==0) firstJ=j; claims++; }
            }
        }
    }

    double acc0=0.0, acc1=0.0, acc2=0.0, acc3=0.0, acc4=0.0, acc5=0.0;
    if (act){
        bool fg = claims > 0;
        int jA = (claims > 1) ? bestJ : firstJ;
        float tbx1=0.f,tby1=0.f,tbx2=0.f,tby2=0.f, maxIou=0.f; int pl=0;
        if (fg){
            float4 t4 = s_cgt[jA];
            tbx1=t4.x; tby1=t4.y; tbx2=t4.z; tby2=t4.w;
            pl = s_clbl[jA];
            maxIou = pair_iou(px1,py1,px2,py2, tbx1,tby1,tbx2,tby2);
        }
        float alMax = fmaxf(bestV, 0.f);
        float soft  = alMax * maxIou / fmaxf(alMax, 1e-9f);
        float w     = fg ? soft : 0.f;
        acc4 = (double)w;

        // classification BCE: background sum + target-class correction
        acc0 = -(double)sumLg;
        if (w > 0.f){
            float pc = clampf(s_cls[tid*21+pl], 1e-7f, 1.f-1e-7f);
            acc0 += (double)(w * (__logf(1.f-pc) - __logf(pc)));
            // CIoU box loss
            acc1 = (double)(w * ciou_loss(px1,py1,px2,py2, tbx1,tby1,tbx2,tby2));
            // DFL loss
            float tgt[4];
            tgt[0] = (ax - tbx1)/st;
            tgt[1] = (ay - tby1)/st;
            tgt[2] = (tbx2 - ax)/st;
            tgt[3] = (tby2 - ay)/st;
            const float4* x4 = reinterpret_cast<const float4*>(pd + ((size_t)b*NA + a)*64);
            float dfl = 0.f;
            #pragma unroll
            for (int s=0;s<4;s++){
                float v[16];
                #pragma unroll
                for (int q=0;q<4;q++){
                    float4 f = x4[s*4+q];
                    v[q*4+0]=f.x; v[q*4+1]=f.y; v[q*4+2]=f.z; v[q*4+3]=f.w;
                }
                float m = v[0];
                #pragma unroll
                for (int j=1;j<16;j++) m = fmaxf(m, v[j]);
                float se = 0.f;
                #pragma unroll
                for (int j=0;j<16;j++) se += __expf(v[j]-m);
                float logZ = m + __logf(se);
                float tg = clampf(tgt[s], 0.f, 14.99f);
                int   tl = (int)tg;
                float wl = (float)(tl+1) - tg;
                dfl += (logZ - v[tl])*wl + (logZ - v[tl+1])*(1.f-wl);
            }
            acc2 = (double)(w * (dfl * 0.25f));
        }
        // aspect-ratio prior loss
        if (fg){
            float gwc = fmaxf(tbx2-tbx1, 1e-4f);
            float ghc = fmaxf(tby2-tby1, 1e-4f);
            if (ghc/gwc >= 1.2f){
                float pwc = fmaxf(px2-px1, 1e-4f);
                float phc = fmaxf(py2-py1, 1e-4f);
                float pen = fmaxf(1.5f - phc/pwc, 0.f) * (1.f - clampf(maxIou,0.f,1.f));
                acc3 = (double)pen;
                acc5 = 1.0;
            }
        }
    }

    // deterministic reduction: warp shfl then per-warp partials
    double accs[6] = {acc0, acc1, acc2, acc3, acc4, acc5};
    #pragma unroll
    for (int k=0;k<6;k++){
        double v = accs[k];
        #pragma unroll
        for (int o=16;o;o>>=1) v += __shfl_down_sync(0xffffffffu, v, o);
        if (lane==0) s_ws[wid*6+k] = v;
    }
    __syncthreads();
    int part = blockIdx.y*MAIN_BX + blockIdx.x;
    if (tid < 6){
        double v = 0.0;
        #pragma unroll
        for (int wq=0;wq<8;wq++) v += s_ws[wq*6+tid];
        g_part[part*6+tid] = v;
        __threadfence();
    }
    __syncthreads();
    if (tid == 0){
        unsigned int prev = atomicAdd(&g_done, 1u);
        s_last = (prev == NPART-1) ? 1 : 0;
    }
    __syncthreads();

    if (s_last){
        // this is the final block: all other blocks' g_part writes are visible
        __threadfence();
        __shared__ double rd[256];
        double v[6] = {0,0,0,0,0,0};
        for (int i=tid; i<NPART; i+=256){
            #pragma unroll
            for (int k=0;k<6;k++) v[k] += g_part[i*6+k];
        }
        double tot[6];
        #pragma unroll
        for (int k=0;k<6;k++){
            rd[tid] = v[k];
            __syncthreads();
            for (int s=128; s>0; s>>=1){
                if (tid < s) rd[tid] += rd[tid+s];
                __syncthreads();
            }
            tot[k] = rd[0];
            __syncthreads();
        }
        if (tid == 0){
            double tss = tot[4] > 1.0 ? tot[4] : 1.0;
            double gc  = tot[5] > 1.0 ? tot[5] : 1.0;
            double total = 7.5*(tot[1]/tss) + 0.5*(tot[0]/tss) + 1.5*(tot[2]/tss) + 0.1*(tot[3]/gc);
            out[0] = (float)total;
            g_done = 0;   // reset for next graph replay
        }
    }
}

extern "C" void kernel_launch(void* const* d_in, const int* in_sizes, int n_in,
                              void* d_out, int out_size){
    (void)in_sizes; (void)n_in; (void)out_size;
    const float* cls   = (const float*)d_in[0];   // [B,A,NC]
    const float* pdist = (const float*)d_in[1];   // [B,A,4,16]
    const float* anc   = (const float*)d_in[2];   // [A,2]
    const float* str   = (const float*)d_in[3];   // [A,1]
    const float* gtb   = (const float*)d_in[4];   // [B,G,4]
    const int*   gtl   = (const int*)d_in[5];     // [B,G]

    k_decode<<<(NB*NA+255)/256, 256>>>(pdist, anc, str);
    k_thresh<<<dim3(NG, NB), 256>>>(cls, gtb, gtl);
    k_main  <<<dim3(MAIN_BX, NB), 256>>>(cls, pdist, anc, str, gtb, gtl, (float*)d_out);
}

// round 4
// speedup vs baseline: 3.4351x; 1.0869x over previous
#include <cuda_runtime.h>
#include <math.h>
#include <float.h>

// Problem constants (fixed by reference setup)
#define NB    32
#define NA    8400
#define NCLS  20
#define NG    128
#define NTOPK 10
#define MAIN_BX 33                 // ceil(8400/256)
#define NPART (MAIN_BX*NB)
#define DEC_BLOCKS ((NB*NA)/64)    // 4200, exact

// ---- static scratch (no allocations allowed) ----
static __device__ float  g_pred[(size_t)NB*NA*4];   // pred_xyxy px (4.3 MB)
static __device__ float  g_thresh[NB*NG];           // per-gt topk threshold
static __device__ double g_part[NPART*6];           // block partials
static __device__ unsigned int g_done = 0;          // completion counter (self-resetting)

__device__ __forceinline__ float clampf(float x, float lo, float hi){ return fminf(fmaxf(x,lo),hi); }

__device__ __forceinline__ float stride_of(int a){
    return a < 6400 ? 8.f : (a < 8000 ? 16.f : 32.f);
}

// align value; MUST be the single shared definition used by both passes so
// threshold comparisons are bit-identical.
__device__ __forceinline__ float align_core(float sq,
                                            float px1,float py1,float px2,float py2,
                                            float gx1,float gy1,float gx2,float gy2,float ga){
    float iw = fminf(px2,gx2)-fmaxf(px1,gx1); iw=fmaxf(iw,0.f);
    float ih = fminf(py2,gy2)-fmaxf(py1,gy1); ih=fmaxf(ih,0.f);
    float inter = iw*ih;
    float pa = fmaxf((px2-px1)*(py2-py1),0.f);
    float iou = inter/(pa+ga-inter+1e-7f);
    iou = clampf(iou,0.f,1.f);
    float i2=iou*iou;
    return sq*(i2*i2*i2);
}

__device__ __forceinline__ float pair_iou(float px1,float py1,float px2,float py2,
                                          float tx1,float ty1,float tx2,float ty2){
    float iw = fminf(px2,tx2) - fmaxf(px1,tx1); iw = fmaxf(iw, 0.f);
    float ih = fminf(py2,ty2) - fmaxf(py1,ty1); ih = fmaxf(ih, 0.f);
    float inter = iw*ih;
    float pa = fmaxf((px2-px1)*(py2-py1), 0.f);
    float ta = fmaxf((tx2-tx1)*(ty2-ty1), 0.f);
    return inter / (pa + ta - inter + 1e-7f);
}

__device__ __forceinline__ float ciou_loss(float px1,float py1,float px2,float py2,
                                           float tx1,float ty1,float tx2,float ty2){
    const float eps = 1e-7f;
    float iw = fminf(px2,tx2) - fmaxf(px1,tx1); iw = fmaxf(iw,0.f);
    float ih = fminf(py2,ty2) - fmaxf(py1,ty1); ih = fmaxf(ih,0.f);
    float inter = iw*ih;
    float pw = fmaxf(px2-px1,0.f), ph = fmaxf(py2-py1,0.f);
    float tw = fmaxf(tx2-tx1,0.f), th = fmaxf(ty2-ty1,0.f);
    float uni = pw*ph + tw*th - inter + eps;
    float iou = inter/uni;
    float dx = (px1+px2)*0.5f - (tx1+tx2)*0.5f;
    float dy = (py1+py2)*0.5f - (ty1+ty2)*0.5f;
    float d2 = dx*dx + dy*dy;
    float ew = fmaxf(fmaxf(px2,tx2)-fminf(px1,tx1),0.f);
    float eh = fmaxf(fmaxf(py2,ty2)-fminf(py1,ty1),0.f);
    float c2 = ew*ew + eh*eh + eps;
    float da = atanf(tw/(th+eps)) - atanf(pw/(ph+eps));
    float v  = 0.40528473456935108577f * da*da;   // 4/pi^2
    float av = v / (1.f - iou + v + eps);
    return 1.f - (iou - d2/c2 - av*v);
}

// ---------------- Stage A: DFL decode -> pred boxes (px), coalesced ----------------
// Block = 256 threads handles 64 anchor-rows (64*256B = 16KB).
// Load: lane-contiguous float4 (4 lines/warp-instr, minimal).
// Compute: thread t = side (t&3) of local anchor (t>>2); 16 floats from smem
// (pitch 17 per 16-group -> conflict-free). Store: 1 float/thread, coalesced.
__global__ void k_decode(const float* __restrict__ pd,
                         const float* __restrict__ anc){
    __shared__ float s[256*17];
    int tid = threadIdx.x;
    int base = blockIdx.x * 64;                 // first anchor-row (i = b*NA+a)
    const float4* src = reinterpret_cast<const float4*>(pd) + (size_t)base*16;
    #pragma unroll
    for (int k=0;k<4;k++){
        int f = tid + k*256;                    // float4 index within block tile
        float4 v = src[f];
        float* dst = s + (f>>2)*17 + (f&3)*4;
        dst[0]=v.x; dst[1]=v.y; dst[2]=v.z; dst[3]=v.w;
    }
    __syncthreads();
    const float* vp = s + tid*17;
    float v0 = vp[0];
    float m = v0;
    #pragma unroll
    for (int j=1;j<16;j++) m = fmaxf(m, vp[j]);
    float se=0.f, sw=0.f;
    #pragma unroll
    for (int j=0;j<16;j++){ float e=__expf(vp[j]-m); se+=e; sw+=e*(float)j; }
    float d = sw/se;
    int i = base + (tid>>2);
    int a = i % NA;
    int sd = tid & 3;
    float st = stride_of(a);
    float coord = ((sd & 1) == 0) ? anc[2*a] : anc[2*a+1];
    float val = ((sd < 2) ? (coord - d) : (coord + d)) * st;
    g_pred[(size_t)base*4 + tid] = val;         // == g_pred[i*4+sd], coalesced
}

// ---------------- Stage B: per-gt topk threshold via rectangle enumeration ----------------
__global__ void k_thresh(const float* __restrict__ cls,
                         const float* __restrict__ gtb,
                         const int*   __restrict__ gtl){
    __shared__ float s_val[1312];
    __shared__ int s_cnt;
    int b = blockIdx.y, g = blockIdx.x, tid = threadIdx.x;
    int lane = tid & 31;
    int lbl = gtl[b*NG+g];
    if (lbl < 0){ if (tid==0) g_thresh[b*NG+g] = 0.f; return; }
    int lc = lbl > NCLS-1 ? NCLS-1 : lbl;
    float4 gb = *reinterpret_cast<const float4*>(gtb + ((size_t)(b*NG+g))*4);
    float gx1=gb.x, gy1=gb.y, gx2=gb.z, gy2=gb.w;
    float ga = fmaxf((gx2-gx1)*(gy2-gy1), 0.f);
    if (tid==0) s_cnt=0;
    __syncthreads();
    const float* pr = g_pred + (size_t)b*NA*4;
    const float* cl = cls + (size_t)b*NA*NCLS;
    const int soff[3] = {0, 6400, 8000};
    const int sn[3]   = {80, 40, 20};
    const float sfv[3]= {8.f, 16.f, 32.f};
    #pragma unroll
    for (int si=0; si<3; si++){
        float s = sfv[si]; int n = sn[si];
        int ix0 = (int)floorf(gx1/s - 0.5f) - 1; if (ix0 < 0)   ix0 = 0;
        int ix1 = (int)ceilf (gx2/s - 0.5f) + 1; if (ix1 > n-1) ix1 = n-1;
        int iy0 = (int)floorf(gy1/s - 0.5f) - 1; if (iy0 < 0)   iy0 = 0;
        int iy1 = (int)ceilf (gy2/s - 0.5f) + 1; if (iy1 > n-1) iy1 = n-1;
        int w = ix1-ix0+1, h = iy1-iy0+1;
        if (w <= 0 || h <= 0) continue;
        int cells = w*h;
        int iters = (cells + 255) / 256;
        for (int it = 0; it < iters; it++){
            int c = it*256 + tid;
            bool inbox = false;
            float al = 0.f;
            if (c < cells){
                int ix = ix0 + c % w;
                int iy = iy0 + c / w;
                float ax = ((float)ix + 0.5f)*s;   // exact, same bits as anc*str
                float ay = ((float)iy + 0.5f)*s;
                if (ax>gx1 && ax<gx2 && ay>gy1 && ay<gy2){
                    int a = soff[si] + iy*n + ix;
                    float4 p = *reinterpret_cast<const float4*>(pr + (size_t)a*4);
                    float sq = sqrtf(clampf(cl[(size_t)a*NCLS + lc], 0.f, 1.f));
                    al = align_core(sq, p.x,p.y,p.z,p.w, gx1,gy1,gx2,gy2, ga);
                    inbox = true;
                }
            }
            // warp-aggregated append
            unsigned msk = __ballot_sync(0xffffffffu, inbox);
            int base = 0;
            if (msk && lane == __ffs(msk)-1)
                base = atomicAdd(&s_cnt, __popc(msk));
            base = __shfl_sync(0xffffffffu, base, msk ? (__ffs(msk)-1) : 0);
            if (inbox){
                int idx = base + __popc(msk & ((1u<<lane)-1u));
                if (idx < 1312) s_val[idx] = al;
            }
        }
    }
    __syncthreads();
    int m = s_cnt; if (m > 1312) m = 1312;
    if (tid < 32){
        float th = 0.f;
        if (m >= NTOPK){
            float t = FLT_MAX;
            #pragma unroll 1
            for (int iter=0; iter<NTOPK; iter++){
                float mx = -1.f;
                for (int j=tid; j<m; j+=32){
                    float v = s_val[j];
                    if (v < t && v > mx) mx = v;
                }
                #pragma unroll
                for (int o=16;o;o>>=1) mx = fmaxf(mx, __shfl_xor_sync(0xffffffffu, mx, o));
                int c = 0;
                for (int j=tid; j<m; j+=32) c += (s_val[j] >= mx);
                #pragma unroll
                for (int o=16;o;o>>=1) c += __shfl_xor_sync(0xffffffffu, c, o);
                th = mx;
                if (c >= NTOPK) break;
                t = mx;
            }
        }
        if (tid==0) g_thresh[b*NG+g] = th;
    }
}

// ---------------- Stage C: per-anchor assignment + fused losses + final combine ----------------
__global__ void k_main(const float* __restrict__ cls,
                       const float* __restrict__ pd,
                       const float* __restrict__ anc,
                       const float* __restrict__ gtb,
                       const int*   __restrict__ gtl,
                       float* __restrict__ out){
    __shared__ float  s_cls[256*21];    // raw cls per thread, pitch 21 (conflict-free)
    __shared__ float4 s_cgt[NG];        // compacted gt boxes (ascending g order)
    __shared__ float  s_cth[NG];
    __shared__ int    s_clbl[NG];
    __shared__ float  s_f[32];
    __shared__ int    s_wcnt[8];
    __shared__ int    s_M;
    __shared__ double s_ws[8*6];
    __shared__ float  s_bb[4];
    __shared__ int    s_last;

    int b = blockIdx.y, tid = threadIdx.x;
    int a = blockIdx.x*256 + tid;
    bool act = a < NA;
    int lane = tid & 31, wid = tid >> 5;

    float st=8.f, ax=0.f, ay=0.f;
    float px1=0.f,py1=0.f,px2=0.f,py2=0.f;
    float sumLg = 0.f;                  // sum of log(1-p) over all classes
    if (act){
        st = stride_of(a);
        ax = anc[2*a]*st; ay = anc[2*a+1]*st;
        float4 p = *reinterpret_cast<const float4*>(g_pred + ((size_t)b*NA+a)*4);
        px1=p.x; py1=p.y; px2=p.z; py2=p.w;
        const float4* cp4 = reinterpret_cast<const float4*>(cls + ((size_t)b*NA+a)*NCLS);
        #pragma unroll
        for (int q=0;q<5;q++){
            float4 f = cp4[q];
            s_cls[tid*21+q*4+0]=f.x; s_cls[tid*21+q*4+1]=f.y;
            s_cls[tid*21+q*4+2]=f.z; s_cls[tid*21+q*4+3]=f.w;
            // grouped: log((1-a)(1-b)(1-c)(1-d)); each factor >= 1e-7 => prod >= 1e-28
            float g0 = 1.f - clampf(f.x,1e-7f,1.f-1e-7f);
            float g1 = 1.f - clampf(f.y,1e-7f,1.f-1e-7f);
            float g2 = 1.f - clampf(f.z,1e-7f,1.f-1e-7f);
            float g3 = 1.f - clampf(f.w,1e-7f,1.f-1e-7f);
            sumLg += __logf((g0*g1)*(g2*g3));
        }
    }

    // block bbox of active anchor centers
    float axm = act?ax: FLT_MAX, axM = act?ax:-FLT_MAX;
    float aym = act?ay: FLT_MAX, ayM = act?ay:-FLT_MAX;
    #pragma unroll
    for (int o=16;o;o>>=1){
        axm = fminf(axm, __shfl_xor_sync(0xffffffffu, axm, o));
        axM = fmaxf(axM, __shfl_xor_sync(0xffffffffu, axM, o));
        aym = fminf(aym, __shfl_xor_sync(0xffffffffu, aym, o));
        ayM = fmaxf(ayM, __shfl_xor_sync(0xffffffffu, ayM, o));
    }
    if (lane==0){ s_f[wid]=axm; s_f[8+wid]=axM; s_f[16+wid]=aym; s_f[24+wid]=ayM; }
    __syncthreads();
    if (tid==0){
        float a0=FLT_MAX,a1=-FLT_MAX,a2=FLT_MAX,a3=-FLT_MAX;
        #pragma unroll
        for (int wq=0;wq<8;wq++){
            a0=fminf(a0,s_f[wq]);    a1=fmaxf(a1,s_f[8+wq]);
            a2=fminf(a2,s_f[16+wq]); a3=fmaxf(a3,s_f[24+wq]);
        }
        s_bb[0]=a0; s_bb[1]=a1; s_bb[2]=a2; s_bb[3]=a3;
    }
    __syncthreads();
    float bxm=s_bb[0], bxM=s_bb[1], bym=s_bb[2], byM=s_bb[3];

    // ordered compaction of candidate gts (tid<128 tests gt=tid)
    bool ok = false; int l = 0; float4 gq4 = make_float4(0,0,0,0); float thv = 0.f;
    if (tid < 128){
        l = gtl[b*NG+tid];
        gq4 = *reinterpret_cast<const float4*>(gtb + ((size_t)(b*NG+tid))*4);
        thv = g_thresh[b*NG+tid];
        ok = (l >= 0) && (gq4.x < bxM) && (gq4.z > bxm) && (gq4.y < byM) && (gq4.w > bym);
    }
    unsigned bal = __ballot_sync(0xffffffffu, ok);
    int pre = __popc(bal & ((1u<<lane)-1u));
    if (lane==0) s_wcnt[wid] = __popc(bal);
    __syncthreads();
    if (tid==0){
        int tot=0;
        #pragma unroll
        for (int wq=0;wq<8;wq++){ int c=s_wcnt[wq]; s_wcnt[wq]=tot; tot+=c; }
        s_M = tot;
    }
    __syncthreads();
    if (ok){
        int pos = s_wcnt[wid] + pre;
        s_cgt[pos] = gq4;
        s_cth[pos] = thv;
        s_clbl[pos] = (l > NCLS-1) ? NCLS-1 : l;
    }
    __syncthreads();
    int M = s_M;

    // main assignment loop over compacted gts
    float bestV = -1.f; int bestJ = 0, firstJ = 0; int claims = 0;
    if (act){
        for (int j=0; j<M; j++){
            float4 gq = s_cgt[j];
            if (ax>gq.x && ax<gq.z && ay>gq.y && ay<gq.w){
                float ga = fmaxf((gq.z-gq.x)*(gq.w-gq.y), 0.f);
                float sq = sqrtf(clampf(s_cls[tid*21 + s_clbl[j]], 0.f, 1.f));
                float al = align_core(sq, px1,py1,px2,py2, gq.x,gq.y,gq.z,gq.w, ga);
                if (al > bestV){ bestV=al; bestJ=j; }
                if (al >= s_cth[j]){ if (claims==0) firstJ=j; claims++; }
            }
        }
    }

    double acc0=0.0, acc1=0.0, acc2=0.0, acc3=0.0, acc4=0.0, acc5=0.0;
    if (act){
        bool fg = claims > 0;
        int jA = (claims > 1) ? bestJ : firstJ;
        float tbx1=0.f,tby1=0.f,tbx2=0.f,tby2=0.f, maxIou=0.f; int pl=0;
        if (fg){
            float4 t4 = s_cgt[jA];
            tbx1=t4.x; tby1=t4.y; tbx2=t4.z; tby2=t4.w;
            pl = s_clbl[jA];
            maxIou = pair_iou(px1,py1,px2,py2, tbx1,tby1,tbx2,tby2);
        }
        float alMax = fmaxf(bestV, 0.f);
        float soft  = alMax * maxIou / fmaxf(alMax, 1e-9f);
        float w     = fg ? soft : 0.f;
        acc4 = (double)w;

        // classification BCE: background sum + target-class correction
        acc0 = -(double)sumLg;
        if (w > 0.f){
            float pc = clampf(s_cls[tid*21+pl], 1e-7f, 1.f-1e-7f);
            acc0 += (double)(w * (__logf(1.f-pc) - __logf(pc)));
            // CIoU box loss
            acc1 = (double)(w * ciou_loss(px1,py1,px2,py2, tbx1,tby1,tbx2,tby2));
            // DFL loss
            float tgt[4];
            tgt[0] = (ax - tbx1)/st;
            tgt[1] = (ay - tby1)/st;
            tgt[2] = (tbx2 - ax)/st;
            tgt[3] = (tby2 - ay)/st;
            const float4* x4 = reinterpret_cast<const float4*>(pd + ((size_t)b*NA + a)*64);
            float dfl = 0.f;
            #pragma unroll
            for (int s=0;s<4;s++){
                float v[16];
                #pragma unroll
                for (int q=0;q<4;q++){
                    float4 f = x4[s*4+q];
                    v[q*4+0]=f.x; v[q*4+1]=f.y; v[q*4+2]=f.z; v[q*4+3]=f.w;
                }
                float m = v[0];
                #pragma unroll
                for (int j=1;j<16;j++) m = fmaxf(m, v[j]);
                float se = 0.f;
                #pragma unroll
                for (int j=0;j<16;j++) se += __expf(v[j]-m);
                float logZ = m + __logf(se);
                float tg = clampf(tgt[s], 0.f, 14.99f);
                int   tl = (int)tg;
                float wl = (float)(tl+1) - tg;
                dfl += (logZ - v[tl])*wl + (logZ - v[tl+1])*(1.f-wl);
            }
            acc2 = (double)(w * (dfl * 0.25f));
        }
        // aspect-ratio prior loss
        if (fg){
            float gwc = fmaxf(tbx2-tbx1, 1e-4f);
            float ghc = fmaxf(tby2-tby1, 1e-4f);
            if (ghc/gwc >= 1.2f){
                float pwc = fmaxf(px2-px1, 1e-4f);
                float phc = fmaxf(py2-py1, 1e-4f);
                float pen = fmaxf(1.5f - phc/pwc, 0.f) * (1.f - clampf(maxIou,0.f,1.f));
                acc3 = (double)pen;
                acc5 = 1.0;
            }
        }
    }

    // deterministic reduction: warp shfl then per-warp partials
    double accs[6] = {acc0, acc1, acc2, acc3, acc4, acc5};
    #pragma unroll
    for (int k=0;k<6;k++){
        double v = accs[k];
        #pragma unroll
        for (int o=16;o;o>>=1) v += __shfl_down_sync(0xffffffffu, v, o);
        if (lane==0) s_ws[wid*6+k] = v;
    }
    __syncthreads();
    int part = blockIdx.y*MAIN_BX + blockIdx.x;
    if (tid < 6){
        double v = 0.0;
        #pragma unroll
        for (int wq=0;wq<8;wq++) v += s_ws[wq*6+tid];
        g_part[part*6+tid] = v;
        __threadfence();
    }
    __syncthreads();
    if (tid == 0){
        unsigned int prev = atomicAdd(&g_done, 1u);
        s_last = (prev == NPART-1) ? 1 : 0;
    }
    __syncthreads();

    if (s_last){
        // this is the final block: all other blocks' g_part writes are visible
        __threadfence();
        __shared__ double rd[256];
        double v[6] = {0,0,0,0,0,0};
        for (int i=tid; i<NPART; i+=256){
            #pragma unroll
            for (int k=0;k<6;k++) v[k] += g_part[i*6+k];
        }
        double tot[6];
        #pragma unroll
        for (int k=0;k<6;k++){
            rd[tid] = v[k];
            __syncthreads();
            for (int s=128; s>0; s>>=1){
                if (tid < s) rd[tid] += rd[tid+s];
                __syncthreads();
            }
            tot[k] = rd[0];
            __syncthreads();
        }
        if (tid == 0){
            double tss = tot[4] > 1.0 ? tot[4] : 1.0;
            double gc  = tot[5] > 1.0 ? tot[5] : 1.0;
            double total = 7.5*(tot[1]/tss) + 0.5*(tot[0]/tss) + 1.5*(tot[2]/tss) + 0.1*(tot[3]/gc);
            out[0] = (float)total;
            g_done = 0;   // reset for next graph replay
        }
    }
}

extern "C" void kernel_launch(void* const* d_in, const int* in_sizes, int n_in,
                              void* d_out, int out_size){
    (void)in_sizes; (void)n_in; (void)out_size;
    const float* cls   = (const float*)d_in[0];   // [B,A,NC]
    const float* pdist = (const float*)d_in[1];   // [B,A,4,16]
    const float* anc   = (const float*)d_in[2];   // [A,2]
    const float* gtb   = (const float*)d_in[4];   // [B,G,4]
    const int*   gtl   = (const int*)d_in[5];     // [B,G]

    k_decode<<<DEC_BLOCKS, 256>>>(pdist, anc);
    k_thresh<<<dim3(NG, NB), 256>>>(cls, gtb, gtl);
    k_main  <<<dim3(MAIN_BX, NB), 256>>>(cls, pdist, anc, gtb, gtl, (float*)d_out);
}

// round 6
// speedup vs baseline: 3.5859x; 1.0439x over previous
#include <cuda_runtime.h>
#include <math.h>
#include <float.h>

// Problem constants (fixed by reference setup)
#define NB    32
#define NA    8400
#define NCLS  20
#define NG    128
#define NTOPK 10
#define MAIN_BX 33                 // ceil(8400/256)
#define NPART (MAIN_BX*NB)
#define DEC_BLOCKS ((NB*NA)/64)    // 4200, exact

// ---- static scratch (no allocations allowed) ----
static __device__ float  g_pred[(size_t)NB*NA*4];   // pred_xyxy px (4.3 MB)
static __device__ float  g_thresh[NB*NG];           // per-gt topk threshold
static __device__ double g_part[NPART*6];           // block partials
static __device__ unsigned int g_done = 0;          // completion counter (self-resetting)

__device__ __forceinline__ float clampf(float x, float lo, float hi){ return fminf(fmaxf(x,lo),hi); }

__device__ __forceinline__ float stride_of(int a){
    return a < 6400 ? 8.f : (a < 8000 ? 16.f : 32.f);
}

// align value; MUST be the single shared definition used by both passes so
// threshold comparisons are bit-identical.
__device__ __forceinline__ float align_core(float sq,
                                            float px1,float py1,float px2,float py2,
                                            float gx1,float gy1,float gx2,float gy2,float ga){
    float iw = fminf(px2,gx2)-fmaxf(px1,gx1); iw=fmaxf(iw,0.f);
    float ih = fminf(py2,gy2)-fmaxf(py1,gy1); ih=fmaxf(ih,0.f);
    float inter = iw*ih;
    float pa = fmaxf((px2-px1)*(py2-py1),0.f);
    float iou = inter/(pa+ga-inter+1e-7f);
    iou = clampf(iou,0.f,1.f);
    float i2=iou*iou;
    return sq*(i2*i2*i2);
}

__device__ __forceinline__ float pair_iou(float px1,float py1,float px2,float py2,
                                          float tx1,float ty1,float tx2,float ty2){
    float iw = fminf(px2,tx2) - fmaxf(px1,tx1); iw = fmaxf(iw, 0.f);
    float ih = fminf(py2,ty2) - fmaxf(py1,ty1); ih = fmaxf(ih, 0.f);
    float inter = iw*ih;
    float pa = fmaxf((px2-px1)*(py2-py1), 0.f);
    float ta = fmaxf((tx2-tx1)*(ty2-ty1), 0.f);
    return inter / (pa + ta - inter + 1e-7f);
}

__device__ __forceinline__ float ciou_loss(float px1,float py1,float px2,float py2,
                                           float tx1,float ty1,float tx2,float ty2){
    const float eps = 1e-7f;
    float iw = fminf(px2,tx2) - fmaxf(px1,tx1); iw = fmaxf(iw,0.f);
    float ih = fminf(py2,ty2) - fmaxf(py1,ty1); ih = fmaxf(ih,0.f);
    float inter = iw*ih;
    float pw = fmaxf(px2-px1,0.f), ph = fmaxf(py2-py1,0.f);
    float tw = fmaxf(tx2-tx1,0.f), th = fmaxf(ty2-ty1,0.f);
    float uni = pw*ph + tw*th - inter + eps;
    float iou = inter/uni;
    float dx = (px1+px2)*0.5f - (tx1+tx2)*0.5f;
    float dy = (py1+py2)*0.5f - (ty1+ty2)*0.5f;
    float d2 = dx*dx + dy*dy;
    float ew = fmaxf(fmaxf(px2,tx2)-fminf(px1,tx1),0.f);
    float eh = fmaxf(fmaxf(py2,ty2)-fminf(py1,ty1),0.f);
    float c2 = ew*ew + eh*eh + eps;
    float da = atanf(tw/(th+eps)) - atanf(pw/(ph+eps));
    float v  = 0.40528473456935108577f * da*da;   // 4/pi^2
    float av = v / (1.f - iou + v + eps);
    return 1.f - (iou - d2/c2 - av*v);
}

// ---------------- Stage A: DFL decode -> pred boxes (px), coalesced ----------------
// Block = 256 threads handles 64 anchor-rows (64*256B = 16KB).
// Staging layout: 256 groups of 16 floats at pitch 20 (80B, 16B-aligned).
//  - writes: STS.128
//  - reads:  4x LDS.128 per thread; word = 5*lane + j covers all 8 bank quads
__global__ void k_decode(const float* __restrict__ pd,
                         const float* __restrict__ anc){
    __shared__ float s[256*20];
    int tid = threadIdx.x;
    int base = blockIdx.x * 64;                 // first anchor-row (i = b*NA+a)
    const float4* src = reinterpret_cast<const float4*>(pd) + (size_t)base*16;
    #pragma unroll
    for (int k=0;k<4;k++){
        int f = tid + k*256;                    // float4 index within block tile
        float4 v = __ldcs(&src[f]);
        *reinterpret_cast<float4*>(s + (f>>2)*20 + (f&3)*4) = v;
    }
    __syncthreads();
    const float* vp = s + tid*20;
    float4 q0 = *reinterpret_cast<const float4*>(vp);
    float4 q1 = *reinterpret_cast<const float4*>(vp+4);
    float4 q2 = *reinterpret_cast<const float4*>(vp+8);
    float4 q3 = *reinterpret_cast<const float4*>(vp+12);
    float v[16] = {q0.x,q0.y,q0.z,q0.w, q1.x,q1.y,q1.z,q1.w,
                   q2.x,q2.y,q2.z,q2.w, q3.x,q3.y,q3.z,q3.w};
    float m = v[0];
    #pragma unroll
    for (int j=1;j<16;j++) m = fmaxf(m, v[j]);
    float se=0.f, sw=0.f;
    #pragma unroll
    for (int j=0;j<16;j++){ float e=__expf(v[j]-m); se+=e; sw+=e*(float)j; }
    float d = sw/se;
    int i = base + (tid>>2);
    int a = i % NA;
    int sd = tid & 3;
    float st = stride_of(a);
    float coord = ((sd & 1) == 0) ? anc[2*a] : anc[2*a+1];
    float val = ((sd < 2) ? (coord - d) : (coord + d)) * st;
    g_pred[(size_t)base*4 + tid] = val;         // == g_pred[i*4+sd], coalesced
}

// ---------------- Stage B: per-gt topk threshold via rectangle enumeration ----------------
__global__ void k_thresh(const float* __restrict__ cls,
                         const float* __restrict__ gtb,
                         const int*   __restrict__ gtl){
    __shared__ float s_val[1312];
    __shared__ int s_cnt;
    int b = blockIdx.y, g = blockIdx.x, tid = threadIdx.x;
    int lane = tid & 31;
    int lbl = gtl[b*NG+g];
    if (lbl < 0){ if (tid==0) g_thresh[b*NG+g] = 0.f; return; }
    int lc = lbl > NCLS-1 ? NCLS-1 : lbl;
    float4 gb = *reinterpret_cast<const float4*>(gtb + ((size_t)(b*NG+g))*4);
    float gx1=gb.x, gy1=gb.y, gx2=gb.z, gy2=gb.w;
    float ga = fmaxf((gx2-gx1)*(gy2-gy1), 0.f);
    if (tid==0) s_cnt=0;
    __syncthreads();
    const float* pr = g_pred + (size_t)b*NA*4;
    const float* cl = cls + (size_t)b*NA*NCLS;
    const int soff[3] = {0, 6400, 8000};
    const int sn[3]   = {80, 40, 20};
    const float sfv[3]= {8.f, 16.f, 32.f};
    #pragma unroll
    for (int si=0; si<3; si++){
        float s = sfv[si]; int n = sn[si];
        int ix0 = (int)floorf(gx1/s - 0.5f) - 1; if (ix0 < 0)   ix0 = 0;
        int ix1 = (int)ceilf (gx2/s - 0.5f) + 1; if (ix1 > n-1) ix1 = n-1;
        int iy0 = (int)floorf(gy1/s - 0.5f) - 1; if (iy0 < 0)   iy0 = 0;
        int iy1 = (int)ceilf (gy2/s - 0.5f) + 1; if (iy1 > n-1) iy1 = n-1;
        int w = ix1-ix0+1, h = iy1-iy0+1;
        if (w <= 0 || h <= 0) continue;
        int cells = w*h;
        int iters = (cells + 255) / 256;
        for (int it = 0; it < iters; it++){
            int c = it*256 + tid;
            bool inbox = false;
            float al = 0.f;
            if (c < cells){
                int ix = ix0 + c % w;
                int iy = iy0 + c / w;
                float ax = ((float)ix + 0.5f)*s;   // exact, same bits as anc*str
                float ay = ((float)iy + 0.5f)*s;
                if (ax>gx1 && ax<gx2 && ay>gy1 && ay<gy2){
                    int a = soff[si] + iy*n + ix;
                    float4 p = *reinterpret_cast<const float4*>(pr + (size_t)a*4);
                    float sq = sqrtf(clampf(cl[(size_t)a*NCLS + lc], 0.f, 1.f));
                    al = align_core(sq, p.x,p.y,p.z,p.w, gx1,gy1,gx2,gy2, ga);
                    inbox = true;
                }
            }
            // warp-aggregated append
            unsigned msk = __ballot_sync(0xffffffffu, inbox);
            int base = 0;
            if (msk && lane == __ffs(msk)-1)
                base = atomicAdd(&s_cnt, __popc(msk));
            base = __shfl_sync(0xffffffffu, base, msk ? (__ffs(msk)-1) : 0);
            if (inbox){
                int idx = base + __popc(msk & ((1u<<lane)-1u));
                if (idx < 1312) s_val[idx] = al;
            }
        }
    }
    __syncthreads();
    int m = s_cnt; if (m > 1312) m = 1312;
    if (tid < 32){
        float th = 0.f;
        if (m >= NTOPK){
            float t = FLT_MAX;
            #pragma unroll 1
            for (int iter=0; iter<NTOPK; iter++){
                float mx = -1.f;
                for (int j=tid; j<m; j+=32){
                    float v = s_val[j];
                    if (v < t && v > mx) mx = v;
                }
                #pragma unroll
                for (int o=16;o;o>>=1) mx = fmaxf(mx, __shfl_xor_sync(0xffffffffu, mx, o));
                int c = 0;
                for (int j=tid; j<m; j+=32) c += (s_val[j] >= mx);
                #pragma unroll
                for (int o=16;o;o>>=1) c += __shfl_xor_sync(0xffffffffu, c, o);
                th = mx;
                if (c >= NTOPK) break;
                t = mx;
            }
        }
        if (tid==0) g_thresh[b*NG+g] = th;
    }
}

// ---------------- Stage C: per-anchor assignment + fused losses + final combine ----------------
__global__ void k_main(const float* __restrict__ cls,
                       const float* __restrict__ pd,
                       const float* __restrict__ anc,
                       const float* __restrict__ gtb,
                       const int*   __restrict__ gtl,
                       float* __restrict__ out){
    __shared__ float  s_cls[256*21];    // raw cls per thread, pitch 21 (conflict-free)
    __shared__ float4 s_cgt[NG];        // compacted gt boxes (ascending g order)
    __shared__ float  s_cth[NG];
    __shared__ int    s_clbl[NG];
    __shared__ float  s_f[32];
    __shared__ int    s_wcnt[8];
    __shared__ int    s_M;
    __shared__ double s_ws[8*6];
    __shared__ float  s_bb[4];
    __shared__ int    s_last;

    int b = blockIdx.y, tid = threadIdx.x;
    int a = blockIdx.x*256 + tid;
    bool act = a < NA;
    int lane = tid & 31, wid = tid >> 5;

    float st=8.f, ax=0.f, ay=0.f;
    float px1=0.f,py1=0.f,px2=0.f,py2=0.f;
    float sumLg = 0.f;                  // sum of log(1-p) over all classes
    if (act){
        st = stride_of(a);
        ax = anc[2*a]*st; ay = anc[2*a+1]*st;
        float4 p = *reinterpret_cast<const float4*>(g_pred + ((size_t)b*NA+a)*4);
        px1=p.x; py1=p.y; px2=p.z; py2=p.w;
        const float4* cp4 = reinterpret_cast<const float4*>(cls + ((size_t)b*NA+a)*NCLS);
        #pragma unroll
        for (int q=0;q<5;q++){
            float4 f = cp4[q];
            s_cls[tid*21+q*4+0]=f.x; s_cls[tid*21+q*4+1]=f.y;
            s_cls[tid*21+q*4+2]=f.z; s_cls[tid*21+q*4+3]=f.w;
            // grouped: log((1-a)(1-b)(1-c)(1-d)); each factor >= 1e-7 => prod >= 1e-28
            float g0 = 1.f - clampf(f.x,1e-7f,1.f-1e-7f);
            float g1 = 1.f - clampf(f.y,1e-7f,1.f-1e-7f);
            float g2 = 1.f - clampf(f.z,1e-7f,1.f-1e-7f);
            float g3 = 1.f - clampf(f.w,1e-7f,1.f-1e-7f);
            sumLg += __logf((g0*g1)*(g2*g3));
        }
    }

    // block bbox of active anchor centers
    float axm = act?ax: FLT_MAX, axM = act?ax:-FLT_MAX;
    float aym = act?ay: FLT_MAX, ayM = act?ay:-FLT_MAX;
    #pragma unroll
    for (int o=16;o;o>>=1){
        axm = fminf(axm, __shfl_xor_sync(0xffffffffu, axm, o));
        axM = fmaxf(axM, __shfl_xor_sync(0xffffffffu, axM, o));
        aym = fminf(aym, __shfl_xor_sync(0xffffffffu, aym, o));
        ayM = fmaxf(ayM, __shfl_xor_sync(0xffffffffu, ayM, o));
    }
    if (lane==0){ s_f[wid]=axm; s_f[8+wid]=axM; s_f[16+wid]=aym; s_f[24+wid]=ayM; }
    __syncthreads();
    if (tid==0){
        float a0=FLT_MAX,a1=-FLT_MAX,a2=FLT_MAX,a3=-FLT_MAX;
        #pragma unroll
        for (int wq=0;wq<8;wq++){
            a0=fminf(a0,s_f[wq]);    a1=fmaxf(a1,s_f[8+wq]);
            a2=fminf(a2,s_f[16+wq]); a3=fmaxf(a3,s_f[24+wq]);
        }
        s_bb[0]=a0; s_bb[1]=a1; s_bb[2]=a2; s_bb[3]=a3;
    }
    __syncthreads();
    float bxm=s_bb[0], bxM=s_bb[1], bym=s_bb[2], byM=s_bb[3];

    // ordered compaction of candidate gts (tid<128 tests gt=tid)
    bool ok = false; int l = 0; float4 gq4 = make_float4(0,0,0,0); float thv = 0.f;
    if (tid < 128){
        l = gtl[b*NG+tid];
        gq4 = *reinterpret_cast<const float4*>(gtb + ((size_t)(b*NG+tid))*4);
        thv = g_thresh[b*NG+tid];
        ok = (l >= 0) && (gq4.x < bxM) && (gq4.z > bxm) && (gq4.y < byM) && (gq4.w > bym);
    }
    unsigned bal = __ballot_sync(0xffffffffu, ok);
    int pre = __popc(bal & ((1u<<lane)-1u));
    if (lane==0) s_wcnt[wid] = __popc(bal);
    __syncthreads();
    if (tid==0){
        int tot=0;
        #pragma unroll
        for (int wq=0;wq<8;wq++){ int c=s_wcnt[wq]; s_wcnt[wq]=tot; tot+=c; }
        s_M = tot;
    }
    __syncthreads();
    if (ok){
        int pos = s_wcnt[wid] + pre;
        s_cgt[pos] = gq4;
        s_cth[pos] = thv;
        s_clbl[pos] = (l > NCLS-1) ? NCLS-1 : l;
    }
    __syncthreads();
    int M = s_M;

    // main assignment loop over compacted gts
    float bestV = -1.f; int bestJ = 0, firstJ = 0; int claims = 0;
    if (act){
        for (int j=0; j<M; j++){
            float4 gq = s_cgt[j];
            if (ax>gq.x && ax<gq.z && ay>gq.y && ay<gq.w){
                float ga = fmaxf((gq.z-gq.x)*(gq.w-gq.y), 0.f);
                float sq = sqrtf(clampf(s_cls[tid*21 + s_clbl[j]], 0.f, 1.f));
                float al = align_core(sq, px1,py1,px2,py2, gq.x,gq.y,gq.z,gq.w, ga);
                if (al > bestV){ bestV=al; bestJ=j; }
                if (al >= s_cth[j]){ if (claims==0) firstJ=j; claims++; }
            }
        }
    }

    float acc0=0.f, acc1=0.f, acc2=0.f, acc3=0.f, acc4=0.f, acc5=0.f;
    if (act){
        bool fg = claims > 0;
        int jA = (claims > 1) ? bestJ : firstJ;
        float tbx1=0.f,tby1=0.f,tbx2=0.f,tby2=0.f, maxIou=0.f; int pl=0;
        if (fg){
            float4 t4 = s_cgt[jA];
            tbx1=t4.x; tby1=t4.y; tbx2=t4.z; tby2=t4.w;
            pl = s_clbl[jA];
            maxIou = pair_iou(px1,py1,px2,py2, tbx1,tby1,tbx2,tby2);
        }
        float alMax = fmaxf(bestV, 0.f);
        float soft  = alMax * maxIou / fmaxf(alMax, 1e-9f);
        float w     = fg ? soft : 0.f;
        acc4 = w;

        // classification BCE: background sum + target-class correction
        acc0 = -sumLg;
        if (w > 0.f){
            float pc = clampf(s_cls[tid*21+pl], 1e-7f, 1.f-1e-7f);
            acc0 += w * (__logf(1.f-pc) - __logf(pc));
            // CIoU box loss
            acc1 = w * ciou_loss(px1,py1,px2,py2, tbx1,tby1,tbx2,tby2);
            // DFL loss
            float tgt[4];
            tgt[0] = (ax - tbx1)/st;
            tgt[1] = (ay - tby1)/st;
            tgt[2] = (tbx2 - ax)/st;
            tgt[3] = (tby2 - ay)/st;
            const float4* x4 = reinterpret_cast<const float4*>(pd + ((size_t)b*NA + a)*64);
            float dfl = 0.f;
            #pragma unroll
            for (int s=0;s<4;s++){
                float v[16];
                #pragma unroll
                for (int q=0;q<4;q++){
                    float4 f = x4[s*4+q];
                    v[q*4+0]=f.x; v[q*4+1]=f.y; v[q*4+2]=f.z; v[q*4+3]=f.w;
                }
                float m = v[0];
                #pragma unroll
                for (int j=1;j<16;j++) m = fmaxf(m, v[j]);
                float se = 0.f;
                #pragma unroll
                for (int j=0;j<16;j++) se += __expf(v[j]-m);
                float logZ = m + __logf(se);
                float tg = clampf(tgt[s], 0.f, 14.99f);
                int   tl = (int)tg;
                float wl = (float)(tl+1) - tg;
                dfl += (logZ - v[tl])*wl + (logZ - v[tl+1])*(1.f-wl);
            }
            acc2 = w * (dfl * 0.25f);
        }
        // aspect-ratio prior loss
        if (fg){
            float gwc = fmaxf(tbx2-tbx1, 1e-4f);
            float ghc = fmaxf(tby2-tby1, 1e-4f);
            if (ghc/gwc >= 1.2f){
                float pwc = fmaxf(px2-px1, 1e-4f);
                float phc = fmaxf(py2-py1, 1e-4f);
                float pen = fmaxf(1.5f - phc/pwc, 0.f) * (1.f - clampf(maxIou,0.f,1.f));
                acc3 = pen;
                acc5 = 1.f;
            }
        }
    }

    // deterministic reduction: float warp shfl, double across warps/blocks
    float accs[6] = {acc0, acc1, acc2, acc3, acc4, acc5};
    #pragma unroll
    for (int k=0;k<6;k++){
        float v = accs[k];
        #pragma unroll
        for (int o=16;o;o>>=1) v += __shfl_down_sync(0xffffffffu, v, o);
        if (lane==0) s_ws[wid*6+k] = (double)v;
    }
    __syncthreads();
    int part = blockIdx.y*MAIN_BX + blockIdx.x;
    if (tid < 6){
        double v = 0.0;
        #pragma unroll
        for (int wq=0;wq<8;wq++) v += s_ws[wq*6+tid];
        g_part[part*6+tid] = v;
        __threadfence();
    }
    __syncthreads();
    if (tid == 0){
        unsigned int prev = atomicAdd(&g_done, 1u);
        s_last = (prev == NPART-1) ? 1 : 0;
    }
    __syncthreads();

    if (s_last){
        // this is the final block: all other blocks' g_part writes are visible
        __threadfence();
        __shared__ double rd[256];
        double v[6] = {0,0,0,0,0,0};
        for (int i=tid; i<NPART; i+=256){
            #pragma unroll
            for (int k=0;k<6;k++) v[k] += g_part[i*6+k];
        }
        double tot[6];
        #pragma unroll
        for (int k=0;k<6;k++){
            rd[tid] = v[k];
            __syncthreads();
            for (int s=128; s>0; s>>=1){
                if (tid < s) rd[tid] += rd[tid+s];
                __syncthreads();
            }
            tot[k] = rd[0];
            __syncthreads();
        }
        if (tid == 0){
            double tss = tot[4] > 1.0 ? tot[4] : 1.0;
            double gc  = tot[5] > 1.0 ? tot[5] : 1.0;
            double total = 7.5*(tot[1]/tss) + 0.5*(tot[0]/tss) + 1.5*(tot[2]/tss) + 0.1*(tot[3]/gc);
            out[0] = (float)total;
            g_done = 0;   // reset for next graph replay
        }
    }
}

extern "C" void kernel_launch(void* const* d_in, const int* in_sizes, int n_in,
                              void* d_out, int out_size){
    (void)in_sizes; (void)n_in; (void)out_size;
    const float* cls   = (const float*)d_in[0];   // [B,A,NC]
    const float* pdist = (const float*)d_in[1];   // [B,A,4,16]
    const float* anc   = (const float*)d_in[2];   // [A,2]
    const float* gtb   = (const float*)d_in[4];   // [B,G,4]
    const int*   gtl   = (const int*)d_in[5];     // [B,G]

    k_decode<<<DEC_BLOCKS, 256>>>(pdist, anc);
    k_thresh<<<dim3(NG, NB), 256>>>(cls, gtb, gtl);
    k_main  <<<dim3(MAIN_BX, NB), 256>>>(cls, pdist, anc, gtb, gtl, (float*)d_out);
}